// round 9
// baseline (speedup 1.0000x reference)
#include <cuda_runtime.h>
#include <cuda_fp16.h>
#include <math.h>
#include <stdint.h>

// ---------------------------------------------------------------------------
// Problem constants (LlamaAttention: B=2,S=1024,P=1024,E=2048,H=32,KV=8,HD=64)
// ---------------------------------------------------------------------------
constexpr int B_   = 2;
constexpr int S_   = 1024;
constexpr int P_   = 1024;
constexpr int E_   = 2048;
constexpr int H_   = 32;
constexpr int KV_  = 8;
constexpr int HD_  = 64;
constexpr int G_   = H_ / KV_;        // 4
constexpr int CTX_ = P_ + S_;         // 2048
constexpr int M_   = B_ * S_;         // 2048 rows of tokens

// ---------------------------------------------------------------------------
// Scratch (static device allocations are the sanctioned workaround)
// ---------------------------------------------------------------------------
__device__ float    g_Q[(size_t)M_ * E_];                   // fp32 Q (pre-rope)
__device__ float    g_K[(size_t)M_ * KV_ * HD_];            // fp32 new K (pre-rope)
__device__ float    g_V[(size_t)M_ * KV_ * HD_];            // fp32 new V
__device__ uint2    g_Xp[(size_t)M_ * E_ / 2];              // x as fp16 (hi,lo) pairs
__device__ uint2    g_Ap[(size_t)M_ * E_ / 2];              // attn out fp16 pairs
__device__ uint32_t g_Wq16[(size_t)E_ * E_ / 2];            // fp16 packed weights
__device__ uint32_t g_Wk16[(size_t)KV_ * HD_ * E_ / 2];
__device__ uint32_t g_Wv16[(size_t)KV_ * HD_ * E_ / 2];
__device__ uint32_t g_Wo16[(size_t)E_ * E_ / 2];
__device__ uint2    g_Qhl[(size_t)M_ * H_ * 32];            // split Q fp16 pairs
__device__ uint32_t g_K16[(size_t)B_ * KV_ * CTX_ * 32];    // K fp16 [b][kv][t][hd/2]
__device__ uint32_t g_Vt16[(size_t)B_ * KV_ * HD_ * (CTX_/2)]; // V^T fp16 [b][kv][hd][t/2]

// ---------------------------------------------------------------------------
// fp16 split helpers
// ---------------------------------------------------------------------------
__device__ __forceinline__ uint2 split2h(float a, float b)
{
    __half2 h = __floats2half2_rn(a, b);
    float ra = a - __low2float(h);
    float rb = b - __high2float(h);
    __half2 l = __floats2half2_rn(ra, rb);
    uint2 r;
    r.x = *reinterpret_cast<uint32_t*>(&h);
    r.y = *reinterpret_cast<uint32_t*>(&l);
    return r;
}

__device__ __forceinline__ uint32_t h2pack(float a, float b)
{
    __half2 h = __floats2half2_rn(a, b);
    return *reinterpret_cast<uint32_t*>(&h);
}

// fp32-accumulator HMMA (main term)
__device__ __forceinline__ void mma_f16(float c[4],
    uint32_t a0, uint32_t a1, uint32_t a2, uint32_t a3,
    uint32_t b0, uint32_t b1)
{
    asm volatile(
        "mma.sync.aligned.m16n8k16.row.col.f32.f16.f16.f32 "
        "{%0,%1,%2,%3}, {%4,%5,%6,%7}, {%8,%9}, {%0,%1,%2,%3};"
        : "+f"(c[0]), "+f"(c[1]), "+f"(c[2]), "+f"(c[3])
        : "r"(a0), "r"(a1), "r"(a2), "r"(a3), "r"(b0), "r"(b1));
}

// fp16-accumulator HMMA (correction term; 2x issue rate)
__device__ __forceinline__ void mma_f16h(uint2& c,
    uint32_t a0, uint32_t a1, uint32_t a2, uint32_t a3,
    uint32_t b0, uint32_t b1)
{
    asm volatile(
        "mma.sync.aligned.m16n8k16.row.col.f16.f16.f16.f16 "
        "{%0,%1}, {%2,%3,%4,%5}, {%6,%7}, {%0,%1};"
        : "+r"(c.x), "+r"(c.y)
        : "r"(a0), "r"(a1), "r"(a2), "r"(a3), "r"(b0), "r"(b1));
}

__device__ __forceinline__ void cp16(void* smem_dst, const void* gsrc)
{
    uint32_t d = (uint32_t)__cvta_generic_to_shared(smem_dst);
    asm volatile("cp.async.cg.shared.global [%0], [%1], 16;" :: "r"(d), "l"(gsrc));
}

// ---------------------------------------------------------------------------
// prep_all: single launch converting x (split pairs) and all weights (fp16).
// grid (8192, 5): y=0 -> x, y=1 -> Wq, y=2 -> Wk, y=3 -> Wv, y=4 -> Wo.
// ---------------------------------------------------------------------------
__global__ void prep_all(const float* __restrict__ x,
                         const float* __restrict__ Wq, const float* __restrict__ Wk,
                         const float* __restrict__ Wv, const float* __restrict__ Wo)
{
    const int i = blockIdx.x * blockDim.x + threadIdx.x;
    const int y = blockIdx.y;
    if (y == 0) {
        float2 f = *(const float2*)(x + 2 * i);
        g_Xp[i] = split2h(f.x, f.y);
    } else if (y == 1) {
        float2 f = *(const float2*)(Wq + 2 * i);
        g_Wq16[i] = h2pack(f.x, f.y);
    } else if (y == 2) {
        if (i < KV_ * HD_ * E_ / 2) {
            float2 f = *(const float2*)(Wk + 2 * i);
            g_Wk16[i] = h2pack(f.x, f.y);
        }
    } else if (y == 3) {
        if (i < KV_ * HD_ * E_ / 2) {
            float2 f = *(const float2*)(Wv + 2 * i);
            g_Wv16[i] = h2pack(f.x, f.y);
        }
    } else {
        float2 f = *(const float2*)(Wo + 2 * i);
        g_Wo16[i] = h2pack(f.x, f.y);
    }
}

// ---------------------------------------------------------------------------
// fp16x2 GEMM:  C[m][n] = sum_k A[m][k] * W[n][k]
// A: fp16 (hi,lo) pairs; W: single fp16. 128x128 tile, BK=32, 256 threads,
// 8 warps (2x4), warp tile 64x32, double-buffered cp.async staging.
// Main term: f32-acc HMMA; correction term: f16-acc HMMA (2x rate),
// folded into the f32 accumulators once in the epilogue.
// ---------------------------------------------------------------------------
constexpr int GSTR2 = 20;             // A stride in uint2 / B stride in uint32 (16 used + 4 pad)
constexpr int A_ST  = 128 * GSTR2;    // uint2 per A stage
constexpr int B_ST  = 128 * GSTR2;    // uint32 per B stage
constexpr int GSM2  = 2 * A_ST * 8 + 2 * B_ST * 4;   // 61440 B

__device__ __forceinline__ void gemm2_stage(
    const uint2* __restrict__ Ap, const uint32_t* __restrict__ Bh,
    int Kp, int bm, int bn, int kp0, uint2* Ad, uint32_t* Bd, int tid)
{
#pragma unroll
    for (int i = 0; i < 4; i++) {
        int c = tid * 4 + i;
        int row = c >> 3, off = c & 7;
        cp16(Ad + row * GSTR2 + off * 2,
             Ap + (size_t)(bm + row) * Kp + kp0 + off * 2);
    }
#pragma unroll
    for (int i = 0; i < 2; i++) {
        int c = tid * 2 + i;
        int row = c >> 2, off = c & 3;
        cp16(Bd + row * GSTR2 + off * 4,
             Bh + (size_t)(bn + row) * Kp + kp0 + off * 4);
    }
    asm volatile("cp.async.commit_group;" ::: "memory");
}

__device__ __forceinline__ void gemm2_core(
    const uint2* __restrict__ Ap, const uint32_t* __restrict__ Bh,
    float* __restrict__ C, int N, int K, int bm, int bn, char* smraw)
{
    uint2*    As = (uint2*)smraw;
    uint32_t* Bs = (uint32_t*)(smraw + 2 * A_ST * 8);
    const int tid  = threadIdx.x;
    const int warp = tid >> 5;
    const int lane = tid & 31;
    const int g    = lane >> 2;
    const int tg   = lane & 3;
    const int wm   = (warp >> 2) * 64;
    const int wn   = (warp & 3) * 32;
    const int Kp   = K / 2;

    float acc[4][4][4];
    uint2 accL[4][4];                     // fp16 correction accumulators
#pragma unroll
    for (int i = 0; i < 4; i++)
#pragma unroll
        for (int j = 0; j < 4; j++) {
            accL[i][j] = make_uint2(0u, 0u);
#pragma unroll
            for (int r = 0; r < 4; r++) acc[i][j][r] = 0.f;
        }

    const int nst = K / 32;
    gemm2_stage(Ap, Bh, Kp, bm, bn, 0,  As,        Bs,        tid);
    gemm2_stage(Ap, Bh, Kp, bm, bn, 16, As + A_ST, Bs + B_ST, tid);

    for (int s = 0; s < nst; s++) {
        const int buf = s & 1;
        if (s < nst - 1)
            asm volatile("cp.async.wait_group 1;" ::: "memory");
        else
            asm volatile("cp.async.wait_group 0;" ::: "memory");
        __syncthreads();

        const uint2*    Ab = As + buf * A_ST;
        const uint32_t* Bb = Bs + buf * B_ST;

#pragma unroll
        for (int ks = 0; ks < 2; ks++) {
            const int kp = ks * 8;
            uint32_t tb[4][2];
#pragma unroll
            for (int nt = 0; nt < 4; nt++) {
                const int cb = wn + nt * 8;
                tb[nt][0] = Bb[(cb + g) * GSTR2 + kp + tg];
                tb[nt][1] = Bb[(cb + g) * GSTR2 + kp + tg + 4];
            }
#pragma unroll
            for (int mt = 0; mt < 4; mt++) {
                const int rb = wm + mt * 16;
                uint2 t0 = Ab[(rb + g)     * GSTR2 + kp + tg];
                uint2 t1 = Ab[(rb + g + 8) * GSTR2 + kp + tg];
                uint2 t2 = Ab[(rb + g)     * GSTR2 + kp + tg + 4];
                uint2 t3 = Ab[(rb + g + 8) * GSTR2 + kp + tg + 4];
#pragma unroll
                for (int nt = 0; nt < 4; nt++) {
                    mma_f16(acc[mt][nt], t0.x, t1.x, t2.x, t3.x,
                            tb[nt][0], tb[nt][1]);
                    mma_f16h(accL[mt][nt], t0.y, t1.y, t2.y, t3.y,
                             tb[nt][0], tb[nt][1]);
                }
            }
        }
        __syncthreads();
        if (s + 2 < nst)
            gemm2_stage(Ap, Bh, Kp, bm, bn, (s + 2) * 16,
                        As + buf * A_ST, Bs + buf * B_ST, tid);
    }

    // epilogue: fold fp16 corrections into fp32 accumulators, store
#pragma unroll
    for (int mt = 0; mt < 4; mt++) {
#pragma unroll
        for (int nt = 0; nt < 4; nt++) {
            float2 f0 = __half22float2(*reinterpret_cast<__half2*>(&accL[mt][nt].x));
            float2 f1 = __half22float2(*reinterpret_cast<__half2*>(&accL[mt][nt].y));
            const int row0 = bm + wm + mt * 16 + g;
            const int col  = bn + wn + nt * 8 + 2 * tg;
            *(float2*)&C[(size_t)row0 * N + col] =
                make_float2(acc[mt][nt][0] + f0.x, acc[mt][nt][1] + f0.y);
            *(float2*)&C[(size_t)(row0 + 8) * N + col] =
                make_float2(acc[mt][nt][2] + f1.x, acc[mt][nt][3] + f1.y);
        }
    }
}

// Fused Q+K+V projection: grid (24, 16). bx<16: Q; 16-19: K; 20-23: V.
__global__ __launch_bounds__(256, 2) void gemm_qkv()
{
    extern __shared__ char smraw[];
    const int bx = blockIdx.x, bm = blockIdx.y * 128;
    if (bx < 16)
        gemm2_core(g_Xp, g_Wq16, g_Q, E_, E_, bm, bx * 128, smraw);
    else if (bx < 20)
        gemm2_core(g_Xp, g_Wk16, g_K, KV_ * HD_, E_, bm, (bx - 16) * 128, smraw);
    else
        gemm2_core(g_Xp, g_Wv16, g_V, KV_ * HD_, E_, bm, (bx - 20) * 128, smraw);
}

__global__ __launch_bounds__(256, 2) void gemm_o(float* __restrict__ out)
{
    extern __shared__ char smraw[];
    gemm2_core(g_Ap, g_Wo16, out, E_, E_, blockIdx.y * 128, blockIdx.x * 128, smraw);
}

// ---------------------------------------------------------------------------
// RoPE + fp16 split: Q -> pairs, new K -> single plane.
// ---------------------------------------------------------------------------
__global__ void rope_split_kernel(const float* __restrict__ cosp,
                                  const float* __restrict__ sinp)
{
    int idx = blockIdx.x * blockDim.x + threadIdx.x;
    constexpr int NH = H_ + KV_;                 // 40
    if (idx >= M_ * NH * 16) return;
    const int p    = idx & 15;
    const int item = idx >> 4;
    const int hh   = item % NH;
    const int row  = item / NH;                  // b*S + s

    const float* cb = cosp + (size_t)row * HD_;
    const float* sb = sinp + (size_t)row * HD_;
    const float c1a = cb[2*p],      c1b = cb[2*p+1];
    const float s1a = sb[2*p],      s1b = sb[2*p+1];
    const float c2a = cb[2*p+32],   c2b = cb[2*p+33];
    const float s2a = sb[2*p+32],   s2b = sb[2*p+33];

    if (hh < H_) {
        const float* base = g_Q + (size_t)row * E_ + hh * HD_;
        uint2* dst = g_Qhl + ((size_t)row * H_ + hh) * 32;
        const float t1a = base[2*p],    t1b = base[2*p+1];
        const float t2a = base[2*p+32], t2b = base[2*p+33];
        dst[p]      = split2h(t1a * c1a - t2a * s1a, t1b * c1b - t2b * s1b);
        dst[p + 16] = split2h(t2a * c2a + t1a * s2a, t2b * c2b + t1b * s2b);
    } else {
        const int kvh = hh - H_;
        const float* base = g_K + (size_t)row * (KV_ * HD_) + kvh * HD_;
        const int b = row / S_, s = row % S_;
        uint32_t* dst = g_K16 + ((size_t)(b * KV_ + kvh) * CTX_ + P_ + s) * 32;
        const float t1a = base[2*p],    t1b = base[2*p+1];
        const float t2a = base[2*p+32], t2b = base[2*p+33];
        dst[p]      = h2pack(t1a * c1a - t2a * s1a, t1b * c1b - t2b * s1b);
        dst[p + 16] = h2pack(t2a * c2a + t1a * s2a, t2b * c2b + t1b * s2b);
    }
}

// ---------------------------------------------------------------------------
// prep_kv: cached K -> fp16 plane; all V -> fp16 transposed plane.
// ---------------------------------------------------------------------------
__global__ __launch_bounds__(256) void prep_kv(
    const float* __restrict__ cache_k, const float* __restrict__ cache_v)
{
    __shared__ float Vs[64][68];
    const int t0 = blockIdx.x * 64;
    const int kv = blockIdx.y, b = blockIdx.z;
    const int tid = threadIdx.x;
    const int row = tid >> 2, q = tid & 3;
    const int t = t0 + row;

    if (t < P_) {
        const float* src = cache_k + ((size_t)(b * KV_ + kv) * CTX_ + t) * HD_ + q * 16;
        uint32_t* dst = g_K16 + ((size_t)(b * KV_ + kv) * CTX_ + t) * 32 + q * 8;
#pragma unroll
        for (int i = 0; i < 4; i++) {
            float4 f = ((const float4*)src)[i];
            dst[2 * i + 0] = h2pack(f.x, f.y);
            dst[2 * i + 1] = h2pack(f.z, f.w);
        }
    }

    const float* vsrc;
    if (t < P_)
        vsrc = cache_v + ((size_t)(b * KV_ + kv) * CTX_ + t) * HD_;
    else
        vsrc = g_V + (size_t)(b * S_ + (t - P_)) * (KV_ * HD_) + kv * HD_;
#pragma unroll
    for (int i = 0; i < 4; i++)
        *(float4*)&Vs[row][q * 16 + 4 * i] = ((const float4*)(vsrc + q * 16))[i];
    __syncthreads();

    const int hd = tid >> 2, c = tid & 3;
    uint32_t* vdst = g_Vt16 + ((size_t)(b * KV_ + kv) * HD_ + hd) * (CTX_ / 2)
                   + t0 / 2 + c * 8;
#pragma unroll
    for (int i = 0; i < 8; i++) {
        const int tp = c * 8 + i;
        vdst[i] = h2pack(Vs[2 * tp][hd], Vs[2 * tp + 1][hd]);
    }
}

// ---------------------------------------------------------------------------
// Flash attention (fp16x2 scores, fp16x1 PV), BLOCK_M=128, 8 warps.
// Grid (S/128, H, B), 256 threads; double-buffered cp.async K/V tiles.
// ---------------------------------------------------------------------------
constexpr int KT = 64 * 36;   // uint32 per K or V tile (stride 36, 32 used)

__global__ __launch_bounds__(256, 2) void attn_mma()
{
    __shared__ uint32_t KsS[2][KT];
    __shared__ uint32_t VtS[2][KT];

    // longest blocks (largest m0) first
    const int mblk = (int)gridDim.x - 1 - (int)blockIdx.x;
    const int m0 = mblk * 128;
    const int h  = blockIdx.y;
    const int b  = blockIdx.z;
    const int kv = h / G_;
    const int tid  = threadIdx.x;
    const int warp = tid >> 5;
    const int lane = tid & 31;
    const int g    = lane >> 2;
    const int tg   = lane & 3;

    const uint32_t* kplane = g_K16 + (size_t)(b * KV_ + kv) * CTX_ * 32;
    const uint32_t* vplane = g_Vt16 + (size_t)(b * KV_ + kv) * HD_ * (CTX_ / 2);
    const int ntile = (P_ + m0 + 128) / 64;

    // tile 0 loads: 512 16B-segments per tile over 256 threads (2 each)
    {
#pragma unroll
        for (int i = 0; i < 2; i++) {
            const int sg = tid + i * 256;
            const int row = sg >> 3, off = (sg & 7) * 4;
            cp16(&KsS[0][row * 36 + off], kplane + (size_t)row * 32 + off);
            cp16(&VtS[0][row * 36 + off], vplane + (size_t)row * (CTX_ / 2) + off);
        }
        asm volatile("cp.async.commit_group;");
    }

    // Q fragments (fp16 hi/lo pairs), persist across tiles
    uint32_t qhi[4][4], qlo[4][4];
    {
        const uint2* q0 = g_Qhl + ((size_t)(b * S_ + m0 + warp * 16 + g)     * H_ + h) * 32;
        const uint2* q8 = g_Qhl + ((size_t)(b * S_ + m0 + warp * 16 + g + 8) * H_ + h) * 32;
#pragma unroll
        for (int ks = 0; ks < 4; ks++) {
            uint2 u0 = q0[tg + 8 * ks];
            uint2 u1 = q8[tg + 8 * ks];
            uint2 u2 = q0[tg + 4 + 8 * ks];
            uint2 u3 = q8[tg + 4 + 8 * ks];
            qhi[ks][0] = u0.x; qhi[ks][1] = u1.x; qhi[ks][2] = u2.x; qhi[ks][3] = u3.x;
            qlo[ks][0] = u0.y; qlo[ks][1] = u1.y; qlo[ks][2] = u2.y; qlo[ks][3] = u3.y;
        }
    }

    float o[8][4];
#pragma unroll
    for (int nt = 0; nt < 8; nt++)
#pragma unroll
        for (int r = 0; r < 4; r++) o[nt][r] = 0.f;
    float m0s = -1e30f, m1s = -1e30f, l0 = 0.f, l1 = 0.f;

    const int qpos0 = P_ + m0 + warp * 16 + g;
    const int wmax  = P_ + m0 + warp * 16 + 15;

    for (int it = 0; it < ntile; ++it) {
        const int t0 = it * 64;
        const int buf = it & 1;

        if (it + 1 < ntile) {
            const int nb = (it + 1) & 1;
#pragma unroll
            for (int i = 0; i < 2; i++) {
                const int sg = tid + i * 256;
                const int row = sg >> 3, off = (sg & 7) * 4;
                cp16(&KsS[nb][row * 36 + off],
                     kplane + (size_t)(t0 + 64 + row) * 32 + off);
                cp16(&VtS[nb][row * 36 + off],
                     vplane + (size_t)row * (CTX_ / 2) + (t0 + 64) / 2 + off);
            }
            asm volatile("cp.async.commit_group;");
            asm volatile("cp.async.wait_group 1;");
        } else {
            asm volatile("cp.async.wait_group 0;");
        }
        __syncthreads();

        if (t0 <= wmax) {
            const uint32_t* KsC = KsS[buf];
            const uint32_t* VtC = VtS[buf];

            // --- scores S = Q K^T (fp16x2): 2 mmas per (ks, nt) ---
            float s[8][4];
#pragma unroll
            for (int nt = 0; nt < 8; nt++)
#pragma unroll
                for (int r = 0; r < 4; r++) s[nt][r] = 0.f;

#pragma unroll
            for (int ks = 0; ks < 4; ks++) {
#pragma unroll
                for (int nt = 0; nt < 8; nt++) {
                    const uint32_t* kb = &KsC[(8 * nt + g) * 36 + 8 * ks + tg];
                    uint32_t b0 = kb[0];
                    uint32_t b1 = kb[4];
                    mma_f16(s[nt], qhi[ks][0], qhi[ks][1], qhi[ks][2], qhi[ks][3], b0, b1);
                    mma_f16(s[nt], qlo[ks][0], qlo[ks][1], qlo[ks][2], qlo[ks][3], b0, b1);
                }
            }

            // --- scale + causal mask ---
            const bool need_mask = (t0 + 63 > P_ + m0 + warp * 16);
            if (need_mask) {
#pragma unroll
                for (int nt = 0; nt < 8; nt++) {
                    const int col = t0 + 8 * nt + 2 * tg;
#pragma unroll
                    for (int r = 0; r < 4; r++) {
                        const int c  = col + (r & 1);
                        const int qp = (r < 2) ? qpos0 : qpos0 + 8;
                        s[nt][r] = (c > qp) ? -1e30f : s[nt][r] * 0.125f;
                    }
                }
            } else {
#pragma unroll
                for (int nt = 0; nt < 8; nt++)
#pragma unroll
                    for (int r = 0; r < 4; r++) s[nt][r] *= 0.125f;
            }

            // --- online softmax ---
            float mx0 = -1e30f, mx1 = -1e30f;
#pragma unroll
            for (int nt = 0; nt < 8; nt++) {
                mx0 = fmaxf(mx0, fmaxf(s[nt][0], s[nt][1]));
                mx1 = fmaxf(mx1, fmaxf(s[nt][2], s[nt][3]));
            }
            mx0 = fmaxf(mx0, __shfl_xor_sync(0xffffffffu, mx0, 1));
            mx0 = fmaxf(mx0, __shfl_xor_sync(0xffffffffu, mx0, 2));
            mx1 = fmaxf(mx1, __shfl_xor_sync(0xffffffffu, mx1, 1));
            mx1 = fmaxf(mx1, __shfl_xor_sync(0xffffffffu, mx1, 2));

            const float mn0 = fmaxf(m0s, mx0);
            const float mn1 = fmaxf(m1s, mx1);
            const float alpha0 = __expf(m0s - mn0);
            const float alpha1 = __expf(m1s - mn1);
            m0s = mn0; m1s = mn1;

            float sum0 = 0.f, sum1 = 0.f;
#pragma unroll
            for (int nt = 0; nt < 8; nt++) {
                s[nt][0] = __expf(s[nt][0] - mn0);
                s[nt][1] = __expf(s[nt][1] - mn0);
                s[nt][2] = __expf(s[nt][2] - mn1);
                s[nt][3] = __expf(s[nt][3] - mn1);
                sum0 += s[nt][0] + s[nt][1];
                sum1 += s[nt][2] + s[nt][3];
            }
            sum0 += __shfl_xor_sync(0xffffffffu, sum0, 1);
            sum0 += __shfl_xor_sync(0xffffffffu, sum0, 2);
            sum1 += __shfl_xor_sync(0xffffffffu, sum1, 1);
            sum1 += __shfl_xor_sync(0xffffffffu, sum1, 2);
            l0 = l0 * alpha0 + sum0;
            l1 = l1 * alpha1 + sum1;

#pragma unroll
            for (int nt = 0; nt < 8; nt++) {
                o[nt][0] *= alpha0; o[nt][1] *= alpha0;
                o[nt][2] *= alpha1; o[nt][3] *= alpha1;
            }

            // --- O += P V (single-fp16 P: 1 mma per (ks, nt)) ---
#pragma unroll
            for (int ks = 0; ks < 4; ks++) {
                uint32_t a0 = h2pack(s[2 * ks][0],     s[2 * ks][1]);
                uint32_t a1 = h2pack(s[2 * ks][2],     s[2 * ks][3]);
                uint32_t a2 = h2pack(s[2 * ks + 1][0], s[2 * ks + 1][1]);
                uint32_t a3 = h2pack(s[2 * ks + 1][2], s[2 * ks + 1][3]);
#pragma unroll
                for (int nt = 0; nt < 8; nt++) {
                    const uint32_t* vb = &VtC[(8 * nt + g) * 36 + 8 * ks + tg];
                    mma_f16(o[nt], a0, a1, a2, a3, vb[0], vb[4]);
                }
            }
        }

        __syncthreads();
    }

    // --- epilogue: write fp16 pairs for the O projection ---
    const float inv0 = 1.f / l0;
    const float inv1 = 1.f / l1;
    const size_t row0  = (size_t)(b * S_ + m0 + warp * 16 + g);
    const size_t base0 = row0 * (E_ / 2) + h * (HD_ / 2) + tg;
    const size_t base8 = base0 + 4 * E_;     // +8 rows (8 * E/2)
#pragma unroll
    for (int nt = 0; nt < 8; nt++) {
        g_Ap[base0 + 4 * nt] = split2h(o[nt][0] * inv0, o[nt][1] * inv0);
        g_Ap[base8 + 4 * nt] = split2h(o[nt][2] * inv1, o[nt][3] * inv1);
    }
}

// ---------------------------------------------------------------------------
// Launcher
// ---------------------------------------------------------------------------
extern "C" void kernel_launch(void* const* d_in, const int* in_sizes, int n_in,
                              void* d_out, int out_size)
{
    const float* x       = (const float*)d_in[0];
    const float* cosp    = (const float*)d_in[1];
    const float* sinp    = (const float*)d_in[2];
    // d_in[3] = mask (causal; computed analytically)
    const float* cache_k = (const float*)d_in[4];
    const float* cache_v = (const float*)d_in[5];
    const float* Wq      = (const float*)d_in[6];
    const float* Wk      = (const float*)d_in[7];
    const float* Wv      = (const float*)d_in[8];
    const float* Wo      = (const float*)d_in[9];
    float* out           = (float*)d_out;

    cudaFuncSetAttribute(gemm_qkv, cudaFuncAttributeMaxDynamicSharedMemorySize, GSM2);
    cudaFuncSetAttribute(gemm_o,   cudaFuncAttributeMaxDynamicSharedMemorySize, GSM2);

    // 0) fp16 planes: x -> (hi,lo) pairs; weights -> single fp16 (one launch)
    prep_all<<<dim3(M_ * E_ / 2 / 256, 5), 256>>>(x, Wq, Wk, Wv, Wo);

    // 1) fused Q/K/V projections (fp16x2 tensor cores, f16-acc corrections)
    gemm_qkv<<<dim3(24, M_ / 128), 256, GSM2>>>();

    // 2) RoPE + fp16 split of Q and new K
    {
        const int total = M_ * (H_ + KV_) * 16;
        rope_split_kernel<<<(total + 255) / 256, 256>>>(cosp, sinp);
    }

    // 3) cached K + all V into fp16 planes (V transposed)
    prep_kv<<<dim3(CTX_ / 64, KV_, B_), 256>>>(cache_k, cache_v);

    // 4) flash attention (fp16x2 QK, fp16 PV, BLOCK_M=128)
    attn_mma<<<dim3(S_ / 128, H_, B_), 256>>>();

    // 5) output projection (fp16x2, f16-acc corrections)
    gemm_o<<<dim3(16, 16), 256, GSM2>>>(out);
}

// round 10
// speedup vs baseline: 1.0866x; 1.0866x over previous
#include <cuda_runtime.h>
#include <cuda_fp16.h>
#include <math.h>
#include <stdint.h>

// ---------------------------------------------------------------------------
// Problem constants (LlamaAttention: B=2,S=1024,P=1024,E=2048,H=32,KV=8,HD=64)
// ---------------------------------------------------------------------------
constexpr int B_   = 2;
constexpr int S_   = 1024;
constexpr int P_   = 1024;
constexpr int E_   = 2048;
constexpr int H_   = 32;
constexpr int KV_  = 8;
constexpr int HD_  = 64;
constexpr int G_   = H_ / KV_;        // 4
constexpr int CTX_ = P_ + S_;         // 2048
constexpr int M_   = B_ * S_;         // 2048 rows of tokens

// ---------------------------------------------------------------------------
// Scratch (static device allocations are the sanctioned workaround)
// ---------------------------------------------------------------------------
__device__ float    g_Q[(size_t)M_ * E_];                   // fp32 Q (pre-rope)
__device__ float    g_K[(size_t)M_ * KV_ * HD_];            // fp32 new K (pre-rope)
__device__ float    g_V[(size_t)M_ * KV_ * HD_];            // fp32 new V
__device__ uint2    g_Xp[(size_t)M_ * E_ / 2];              // x as fp16 (hi,lo) pairs
__device__ uint2    g_Ap[(size_t)M_ * E_ / 2];              // attn out fp16 pairs
__device__ uint32_t g_Wq16[(size_t)E_ * E_ / 2];            // fp16 packed weights
__device__ uint32_t g_Wk16[(size_t)KV_ * HD_ * E_ / 2];
__device__ uint32_t g_Wv16[(size_t)KV_ * HD_ * E_ / 2];
__device__ uint32_t g_Wo16[(size_t)E_ * E_ / 2];
__device__ uint32_t g_Q16[(size_t)M_ * H_ * 32];            // Q fp16 [row][h][hd/2]
__device__ uint32_t g_K16[(size_t)B_ * KV_ * CTX_ * 32];    // K fp16 [b][kv][t][hd/2]
__device__ uint32_t g_Vt16[(size_t)B_ * KV_ * HD_ * (CTX_/2)]; // V^T fp16 [b][kv][hd][t/2]

// ---------------------------------------------------------------------------
// fp16 split helpers
// ---------------------------------------------------------------------------
__device__ __forceinline__ uint2 split2h(float a, float b)
{
    __half2 h = __floats2half2_rn(a, b);
    float ra = a - __low2float(h);
    float rb = b - __high2float(h);
    __half2 l = __floats2half2_rn(ra, rb);
    uint2 r;
    r.x = *reinterpret_cast<uint32_t*>(&h);
    r.y = *reinterpret_cast<uint32_t*>(&l);
    return r;
}

__device__ __forceinline__ uint32_t h2pack(float a, float b)
{
    __half2 h = __floats2half2_rn(a, b);
    return *reinterpret_cast<uint32_t*>(&h);
}

__device__ __forceinline__ void mma_f16(float c[4],
    uint32_t a0, uint32_t a1, uint32_t a2, uint32_t a3,
    uint32_t b0, uint32_t b1)
{
    asm volatile(
        "mma.sync.aligned.m16n8k16.row.col.f32.f16.f16.f32 "
        "{%0,%1,%2,%3}, {%4,%5,%6,%7}, {%8,%9}, {%0,%1,%2,%3};"
        : "+f"(c[0]), "+f"(c[1]), "+f"(c[2]), "+f"(c[3])
        : "r"(a0), "r"(a1), "r"(a2), "r"(a3), "r"(b0), "r"(b1));
}

__device__ __forceinline__ void cp16(void* smem_dst, const void* gsrc)
{
    uint32_t d = (uint32_t)__cvta_generic_to_shared(smem_dst);
    asm volatile("cp.async.cg.shared.global [%0], [%1], 16;" :: "r"(d), "l"(gsrc));
}

// ---------------------------------------------------------------------------
// prep_all: single launch converting x (split pairs) and all weights (fp16).
// grid (8192, 5): y=0 -> x, y=1 -> Wq, y=2 -> Wk, y=3 -> Wv, y=4 -> Wo.
// ---------------------------------------------------------------------------
__global__ void prep_all(const float* __restrict__ x,
                         const float* __restrict__ Wq, const float* __restrict__ Wk,
                         const float* __restrict__ Wv, const float* __restrict__ Wo)
{
    const int i = blockIdx.x * blockDim.x + threadIdx.x;
    const int y = blockIdx.y;
    if (y == 0) {
        float2 f = *(const float2*)(x + 2 * i);
        g_Xp[i] = split2h(f.x, f.y);
    } else if (y == 1) {
        float2 f = *(const float2*)(Wq + 2 * i);
        g_Wq16[i] = h2pack(f.x, f.y);
    } else if (y == 2) {
        if (i < KV_ * HD_ * E_ / 2) {
            float2 f = *(const float2*)(Wk + 2 * i);
            g_Wk16[i] = h2pack(f.x, f.y);
        }
    } else if (y == 3) {
        if (i < KV_ * HD_ * E_ / 2) {
            float2 f = *(const float2*)(Wv + 2 * i);
            g_Wv16[i] = h2pack(f.x, f.y);
        }
    } else {
        float2 f = *(const float2*)(Wo + 2 * i);
        g_Wo16[i] = h2pack(f.x, f.y);
    }
}

// ---------------------------------------------------------------------------
// fp16x2 GEMM:  C[m][n] = sum_k A[m][k] * W[n][k]
// A: fp16 (hi,lo) pairs; W: single fp16. 128x128 tile, BK=32, 256 threads,
// 8 warps (2x4), warp tile 64x32.
// 3-stage cp.async pipeline, ONE __syncthreads per stage.
// ---------------------------------------------------------------------------
constexpr int GSTR2 = 20;             // A stride in uint2 / B stride in uint32
constexpr int A_ST  = 128 * GSTR2;    // uint2 per A stage  (20480 B)
constexpr int B_ST  = 128 * GSTR2;    // uint32 per B stage (10240 B)
constexpr int GSM2  = 3 * (A_ST * 8 + B_ST * 4);   // 92160 B

__device__ __forceinline__ void gemm2_stage(
    const uint2* __restrict__ Ap, const uint32_t* __restrict__ Bh,
    int Kp, int bm, int bn, int kp0, uint2* Ad, uint32_t* Bd, int tid)
{
#pragma unroll
    for (int i = 0; i < 4; i++) {
        int c = tid * 4 + i;
        int row = c >> 3, off = c & 7;
        cp16(Ad + row * GSTR2 + off * 2,
             Ap + (size_t)(bm + row) * Kp + kp0 + off * 2);
    }
#pragma unroll
    for (int i = 0; i < 2; i++) {
        int c = tid * 2 + i;
        int row = c >> 2, off = c & 3;
        cp16(Bd + row * GSTR2 + off * 4,
             Bh + (size_t)(bn + row) * Kp + kp0 + off * 4);
    }
    asm volatile("cp.async.commit_group;" ::: "memory");
}

__device__ __forceinline__ void gemm2_core(
    const uint2* __restrict__ Ap, const uint32_t* __restrict__ Bh,
    float* __restrict__ C, int N, int K, int bm, int bn, char* smraw)
{
    uint2*    As = (uint2*)smraw;
    uint32_t* Bs = (uint32_t*)(smraw + 3 * A_ST * 8);
    const int tid  = threadIdx.x;
    const int warp = tid >> 5;
    const int lane = tid & 31;
    const int g    = lane >> 2;
    const int tg   = lane & 3;
    const int wm   = (warp >> 2) * 64;
    const int wn   = (warp & 3) * 32;
    const int Kp   = K / 2;

    float acc[4][4][4];
#pragma unroll
    for (int i = 0; i < 4; i++)
#pragma unroll
        for (int j = 0; j < 4; j++)
#pragma unroll
            for (int r = 0; r < 4; r++) acc[i][j][r] = 0.f;

    const int nst = K / 32;    // 64
    gemm2_stage(Ap, Bh, Kp, bm, bn, 0,  As,        Bs,        tid);
    gemm2_stage(Ap, Bh, Kp, bm, bn, 16, As + A_ST, Bs + B_ST, tid);

    int buf = 0;               // s % 3
    for (int s = 0; s < nst; s++) {
        if (s + 1 < nst)
            asm volatile("cp.async.wait_group 1;" ::: "memory");
        else
            asm volatile("cp.async.wait_group 0;" ::: "memory");
        __syncthreads();

        // stage s+2 into buffer (s+2)%3 — its last readers were pre-sync (stage s-1)
        if (s + 2 < nst) {
            int nb = buf + 2; if (nb >= 3) nb -= 3;
            gemm2_stage(Ap, Bh, Kp, bm, bn, (s + 2) * 16,
                        As + nb * A_ST, Bs + nb * B_ST, tid);
        }

        const uint2*    Ab = As + buf * A_ST;
        const uint32_t* Bb = Bs + buf * B_ST;

#pragma unroll
        for (int ks = 0; ks < 2; ks++) {
            const int kp = ks * 8;
            uint2 ta[4][4];
#pragma unroll
            for (int mt = 0; mt < 4; mt++) {
                const int rb = wm + mt * 16;
                ta[mt][0] = Ab[(rb + g)     * GSTR2 + kp + tg];
                ta[mt][1] = Ab[(rb + g + 8) * GSTR2 + kp + tg];
                ta[mt][2] = Ab[(rb + g)     * GSTR2 + kp + tg + 4];
                ta[mt][3] = Ab[(rb + g + 8) * GSTR2 + kp + tg + 4];
            }
            uint32_t tb[4][2];
#pragma unroll
            for (int nt = 0; nt < 4; nt++) {
                const int cb = wn + nt * 8;
                tb[nt][0] = Bb[(cb + g) * GSTR2 + kp + tg];
                tb[nt][1] = Bb[(cb + g) * GSTR2 + kp + tg + 4];
            }
#pragma unroll
            for (int mt = 0; mt < 4; mt++) {
#pragma unroll
                for (int nt = 0; nt < 4; nt++) {
                    mma_f16(acc[mt][nt],
                            ta[mt][0].x, ta[mt][1].x, ta[mt][2].x, ta[mt][3].x,
                            tb[nt][0], tb[nt][1]);
                    mma_f16(acc[mt][nt],
                            ta[mt][0].y, ta[mt][1].y, ta[mt][2].y, ta[mt][3].y,
                            tb[nt][0], tb[nt][1]);
                }
            }
        }
        if (++buf == 3) buf = 0;
    }

    // epilogue
#pragma unroll
    for (int mt = 0; mt < 4; mt++) {
#pragma unroll
        for (int nt = 0; nt < 4; nt++) {
            const int row0 = bm + wm + mt * 16 + g;
            const int col  = bn + wn + nt * 8 + 2 * tg;
            *(float2*)&C[(size_t)row0 * N + col] =
                make_float2(acc[mt][nt][0], acc[mt][nt][1]);
            *(float2*)&C[(size_t)(row0 + 8) * N + col] =
                make_float2(acc[mt][nt][2], acc[mt][nt][3]);
        }
    }
}

// Fused Q+K+V projection: grid (24, 16). bx<16: Q; 16-19: K; 20-23: V.
__global__ __launch_bounds__(256, 2) void gemm_qkv()
{
    extern __shared__ char smraw[];
    const int bx = blockIdx.x, bm = blockIdx.y * 128;
    if (bx < 16)
        gemm2_core(g_Xp, g_Wq16, g_Q, E_, E_, bm, bx * 128, smraw);
    else if (bx < 20)
        gemm2_core(g_Xp, g_Wk16, g_K, KV_ * HD_, E_, bm, (bx - 16) * 128, smraw);
    else
        gemm2_core(g_Xp, g_Wv16, g_V, KV_ * HD_, E_, bm, (bx - 20) * 128, smraw);
}

__global__ __launch_bounds__(256, 2) void gemm_o(float* __restrict__ out)
{
    extern __shared__ char smraw[];
    gemm2_core(g_Ap, g_Wo16, out, E_, E_, blockIdx.y * 128, blockIdx.x * 128, smraw);
}

// ---------------------------------------------------------------------------
// RoPE + fp16 convert: Q -> single plane, new K -> single plane.
// ---------------------------------------------------------------------------
__global__ void rope_split_kernel(const float* __restrict__ cosp,
                                  const float* __restrict__ sinp)
{
    int idx = blockIdx.x * blockDim.x + threadIdx.x;
    constexpr int NH = H_ + KV_;                 // 40
    if (idx >= M_ * NH * 16) return;
    const int p    = idx & 15;
    const int item = idx >> 4;
    const int hh   = item % NH;
    const int row  = item / NH;                  // b*S + s

    const float* cb = cosp + (size_t)row * HD_;
    const float* sb = sinp + (size_t)row * HD_;
    const float c1a = cb[2*p],      c1b = cb[2*p+1];
    const float s1a = sb[2*p],      s1b = sb[2*p+1];
    const float c2a = cb[2*p+32],   c2b = cb[2*p+33];
    const float s2a = sb[2*p+32],   s2b = sb[2*p+33];

    const float* base;
    uint32_t* dst;
    if (hh < H_) {
        base = g_Q + (size_t)row * E_ + hh * HD_;
        dst  = g_Q16 + ((size_t)row * H_ + hh) * 32;
    } else {
        const int kvh = hh - H_;
        base = g_K + (size_t)row * (KV_ * HD_) + kvh * HD_;
        const int b = row / S_, s = row % S_;
        dst  = g_K16 + ((size_t)(b * KV_ + kvh) * CTX_ + P_ + s) * 32;
    }
    const float t1a = base[2*p],    t1b = base[2*p+1];
    const float t2a = base[2*p+32], t2b = base[2*p+33];
    dst[p]      = h2pack(t1a * c1a - t2a * s1a, t1b * c1b - t2b * s1b);
    dst[p + 16] = h2pack(t2a * c2a + t1a * s2a, t2b * c2b + t1b * s2b);
}

// ---------------------------------------------------------------------------
// prep_kv: cached K -> fp16 plane; all V -> fp16 transposed plane.
// ---------------------------------------------------------------------------
__global__ __launch_bounds__(256) void prep_kv(
    const float* __restrict__ cache_k, const float* __restrict__ cache_v)
{
    __shared__ float Vs[64][68];
    const int t0 = blockIdx.x * 64;
    const int kv = blockIdx.y, b = blockIdx.z;
    const int tid = threadIdx.x;
    const int row = tid >> 2, q = tid & 3;
    const int t = t0 + row;

    if (t < P_) {
        const float* src = cache_k + ((size_t)(b * KV_ + kv) * CTX_ + t) * HD_ + q * 16;
        uint32_t* dst = g_K16 + ((size_t)(b * KV_ + kv) * CTX_ + t) * 32 + q * 8;
#pragma unroll
        for (int i = 0; i < 4; i++) {
            float4 f = ((const float4*)src)[i];
            dst[2 * i + 0] = h2pack(f.x, f.y);
            dst[2 * i + 1] = h2pack(f.z, f.w);
        }
    }

    const float* vsrc;
    if (t < P_)
        vsrc = cache_v + ((size_t)(b * KV_ + kv) * CTX_ + t) * HD_;
    else
        vsrc = g_V + (size_t)(b * S_ + (t - P_)) * (KV_ * HD_) + kv * HD_;
#pragma unroll
    for (int i = 0; i < 4; i++)
        *(float4*)&Vs[row][q * 16 + 4 * i] = ((const float4*)(vsrc + q * 16))[i];
    __syncthreads();

    const int hd = tid >> 2, c = tid & 3;
    uint32_t* vdst = g_Vt16 + ((size_t)(b * KV_ + kv) * HD_ + hd) * (CTX_ / 2)
                   + t0 / 2 + c * 8;
#pragma unroll
    for (int i = 0; i < 8; i++) {
        const int tp = c * 8 + i;
        vdst[i] = h2pack(Vs[2 * tp][hd], Vs[2 * tp + 1][hd]);
    }
}

// ---------------------------------------------------------------------------
// Flash attention (pure fp16 QK and PV, fp32 accum), BLOCK_M=128, 8 warps.
// Grid (S/128, H, B), 256 threads; double-buffered cp.async K/V tiles.
// ---------------------------------------------------------------------------
constexpr int KT = 64 * 36;   // uint32 per K or V tile (stride 36, 32 used)

__global__ __launch_bounds__(256, 2) void attn_mma()
{
    __shared__ uint32_t KsS[2][KT];
    __shared__ uint32_t VtS[2][KT];

    // longest blocks (largest m0) first
    const int mblk = (int)gridDim.x - 1 - (int)blockIdx.x;
    const int m0 = mblk * 128;
    const int h  = blockIdx.y;
    const int b  = blockIdx.z;
    const int kv = h / G_;
    const int tid  = threadIdx.x;
    const int warp = tid >> 5;
    const int lane = tid & 31;
    const int g    = lane >> 2;
    const int tg   = lane & 3;

    const uint32_t* kplane = g_K16 + (size_t)(b * KV_ + kv) * CTX_ * 32;
    const uint32_t* vplane = g_Vt16 + (size_t)(b * KV_ + kv) * HD_ * (CTX_ / 2);
    const int ntile = (P_ + m0 + 128) / 64;

    // tile 0 loads
    {
#pragma unroll
        for (int i = 0; i < 2; i++) {
            const int sg = tid + i * 256;
            const int row = sg >> 3, off = (sg & 7) * 4;
            cp16(&KsS[0][row * 36 + off], kplane + (size_t)row * 32 + off);
            cp16(&VtS[0][row * 36 + off], vplane + (size_t)row * (CTX_ / 2) + off);
        }
        asm volatile("cp.async.commit_group;");
    }

    // Q fragments (single fp16 plane), persist across tiles
    uint32_t qf[4][4];
    {
        const uint32_t* q0 = g_Q16 + ((size_t)(b * S_ + m0 + warp * 16 + g)     * H_ + h) * 32;
        const uint32_t* q8 = g_Q16 + ((size_t)(b * S_ + m0 + warp * 16 + g + 8) * H_ + h) * 32;
#pragma unroll
        for (int ks = 0; ks < 4; ks++) {
            qf[ks][0] = q0[tg + 8 * ks];
            qf[ks][1] = q8[tg + 8 * ks];
            qf[ks][2] = q0[tg + 4 + 8 * ks];
            qf[ks][3] = q8[tg + 4 + 8 * ks];
        }
    }

    float o[8][4];
#pragma unroll
    for (int nt = 0; nt < 8; nt++)
#pragma unroll
        for (int r = 0; r < 4; r++) o[nt][r] = 0.f;
    float m0s = -1e30f, m1s = -1e30f, l0 = 0.f, l1 = 0.f;

    const int qpos0 = P_ + m0 + warp * 16 + g;
    const int wmax  = P_ + m0 + warp * 16 + 15;

    for (int it = 0; it < ntile; ++it) {
        const int t0 = it * 64;
        const int buf = it & 1;

        if (it + 1 < ntile) {
            const int nb = (it + 1) & 1;
#pragma unroll
            for (int i = 0; i < 2; i++) {
                const int sg = tid + i * 256;
                const int row = sg >> 3, off = (sg & 7) * 4;
                cp16(&KsS[nb][row * 36 + off],
                     kplane + (size_t)(t0 + 64 + row) * 32 + off);
                cp16(&VtS[nb][row * 36 + off],
                     vplane + (size_t)row * (CTX_ / 2) + (t0 + 64) / 2 + off);
            }
            asm volatile("cp.async.commit_group;");
            asm volatile("cp.async.wait_group 1;");
        } else {
            asm volatile("cp.async.wait_group 0;");
        }
        __syncthreads();

        if (t0 <= wmax) {
            const uint32_t* KsC = KsS[buf];
            const uint32_t* VtC = VtS[buf];

            // --- scores S = Q K^T (single fp16 mma per (ks, nt)) ---
            float s[8][4];
#pragma unroll
            for (int nt = 0; nt < 8; nt++)
#pragma unroll
                for (int r = 0; r < 4; r++) s[nt][r] = 0.f;

#pragma unroll
            for (int ks = 0; ks < 4; ks++) {
#pragma unroll
                for (int nt = 0; nt < 8; nt++) {
                    const uint32_t* kb = &KsC[(8 * nt + g) * 36 + 8 * ks + tg];
                    mma_f16(s[nt], qf[ks][0], qf[ks][1], qf[ks][2], qf[ks][3],
                            kb[0], kb[4]);
                }
            }

            // --- scale + causal mask ---
            const bool need_mask = (t0 + 63 > P_ + m0 + warp * 16);
            if (need_mask) {
#pragma unroll
                for (int nt = 0; nt < 8; nt++) {
                    const int col = t0 + 8 * nt + 2 * tg;
#pragma unroll
                    for (int r = 0; r < 4; r++) {
                        const int c  = col + (r & 1);
                        const int qp = (r < 2) ? qpos0 : qpos0 + 8;
                        s[nt][r] = (c > qp) ? -1e30f : s[nt][r] * 0.125f;
                    }
                }
            } else {
#pragma unroll
                for (int nt = 0; nt < 8; nt++)
#pragma unroll
                    for (int r = 0; r < 4; r++) s[nt][r] *= 0.125f;
            }

            // --- online softmax ---
            float mx0 = -1e30f, mx1 = -1e30f;
#pragma unroll
            for (int nt = 0; nt < 8; nt++) {
                mx0 = fmaxf(mx0, fmaxf(s[nt][0], s[nt][1]));
                mx1 = fmaxf(mx1, fmaxf(s[nt][2], s[nt][3]));
            }
            mx0 = fmaxf(mx0, __shfl_xor_sync(0xffffffffu, mx0, 1));
            mx0 = fmaxf(mx0, __shfl_xor_sync(0xffffffffu, mx0, 2));
            mx1 = fmaxf(mx1, __shfl_xor_sync(0xffffffffu, mx1, 1));
            mx1 = fmaxf(mx1, __shfl_xor_sync(0xffffffffu, mx1, 2));

            const float mn0 = fmaxf(m0s, mx0);
            const float mn1 = fmaxf(m1s, mx1);
            const float alpha0 = __expf(m0s - mn0);
            const float alpha1 = __expf(m1s - mn1);
            m0s = mn0; m1s = mn1;

            float sum0 = 0.f, sum1 = 0.f;
#pragma unroll
            for (int nt = 0; nt < 8; nt++) {
                s[nt][0] = __expf(s[nt][0] - mn0);
                s[nt][1] = __expf(s[nt][1] - mn0);
                s[nt][2] = __expf(s[nt][2] - mn1);
                s[nt][3] = __expf(s[nt][3] - mn1);
                sum0 += s[nt][0] + s[nt][1];
                sum1 += s[nt][2] + s[nt][3];
            }
            sum0 += __shfl_xor_sync(0xffffffffu, sum0, 1);
            sum0 += __shfl_xor_sync(0xffffffffu, sum0, 2);
            sum1 += __shfl_xor_sync(0xffffffffu, sum1, 1);
            sum1 += __shfl_xor_sync(0xffffffffu, sum1, 2);
            l0 = l0 * alpha0 + sum0;
            l1 = l1 * alpha1 + sum1;

#pragma unroll
            for (int nt = 0; nt < 8; nt++) {
                o[nt][0] *= alpha0; o[nt][1] *= alpha0;
                o[nt][2] *= alpha1; o[nt][3] *= alpha1;
            }

            // --- O += P V (single-fp16 P: 1 mma per (ks, nt)) ---
#pragma unroll
            for (int ks = 0; ks < 4; ks++) {
                uint32_t a0 = h2pack(s[2 * ks][0],     s[2 * ks][1]);
                uint32_t a1 = h2pack(s[2 * ks][2],     s[2 * ks][3]);
                uint32_t a2 = h2pack(s[2 * ks + 1][0], s[2 * ks + 1][1]);
                uint32_t a3 = h2pack(s[2 * ks + 1][2], s[2 * ks + 1][3]);
#pragma unroll
                for (int nt = 0; nt < 8; nt++) {
                    const uint32_t* vb = &VtC[(8 * nt + g) * 36 + 8 * ks + tg];
                    mma_f16(o[nt], a0, a1, a2, a3, vb[0], vb[4]);
                }
            }
        }

        __syncthreads();
    }

    // --- epilogue: write fp16 pairs for the O projection ---
    const float inv0 = 1.f / l0;
    const float inv1 = 1.f / l1;
    const size_t row0  = (size_t)(b * S_ + m0 + warp * 16 + g);
    const size_t base0 = row0 * (E_ / 2) + h * (HD_ / 2) + tg;
    const size_t base8 = base0 + 4 * E_;     // +8 rows (8 * E/2)
#pragma unroll
    for (int nt = 0; nt < 8; nt++) {
        g_Ap[base0 + 4 * nt] = split2h(o[nt][0] * inv0, o[nt][1] * inv0);
        g_Ap[base8 + 4 * nt] = split2h(o[nt][2] * inv1, o[nt][3] * inv1);
    }
}

// ---------------------------------------------------------------------------
// Launcher
// ---------------------------------------------------------------------------
extern "C" void kernel_launch(void* const* d_in, const int* in_sizes, int n_in,
                              void* d_out, int out_size)
{
    const float* x       = (const float*)d_in[0];
    const float* cosp    = (const float*)d_in[1];
    const float* sinp    = (const float*)d_in[2];
    // d_in[3] = mask (causal; computed analytically)
    const float* cache_k = (const float*)d_in[4];
    const float* cache_v = (const float*)d_in[5];
    const float* Wq      = (const float*)d_in[6];
    const float* Wk      = (const float*)d_in[7];
    const float* Wv      = (const float*)d_in[8];
    const float* Wo      = (const float*)d_in[9];
    float* out           = (float*)d_out;

    cudaFuncSetAttribute(gemm_qkv, cudaFuncAttributeMaxDynamicSharedMemorySize, GSM2);
    cudaFuncSetAttribute(gemm_o,   cudaFuncAttributeMaxDynamicSharedMemorySize, GSM2);

    // 0) fp16 planes: x -> (hi,lo) pairs; weights -> single fp16 (one launch)
    prep_all<<<dim3(M_ * E_ / 2 / 256, 5), 256>>>(x, Wq, Wk, Wv, Wo);

    // 1) fused Q/K/V projections (fp16x2 tensor cores, 3-stage pipeline)
    gemm_qkv<<<dim3(24, M_ / 128), 256, GSM2>>>();

    // 2) RoPE + fp16 convert of Q and new K
    {
        const int total = M_ * (H_ + KV_) * 16;
        rope_split_kernel<<<(total + 255) / 256, 256>>>(cosp, sinp);
    }

    // 3) cached K + all V into fp16 planes (V transposed)
    prep_kv<<<dim3(CTX_ / 64, KV_, B_), 256>>>(cache_k, cache_v);

    // 4) flash attention (pure fp16 mma, BLOCK_M=128)
    attn_mma<<<dim3(S_ / 128, H_, B_), 256>>>();

    // 5) output projection (fp16x2, 3-stage pipeline)
    gemm_o<<<dim3(16, 16), 256, GSM2>>>(out);
}

// round 11
// speedup vs baseline: 1.5907x; 1.4639x over previous
#include <cuda_runtime.h>
#include <cuda_fp16.h>
#include <math.h>
#include <stdint.h>

// ---------------------------------------------------------------------------
// Problem constants (LlamaAttention: B=2,S=1024,P=1024,E=2048,H=32,KV=8,HD=64)
// ---------------------------------------------------------------------------
constexpr int B_   = 2;
constexpr int S_   = 1024;
constexpr int P_   = 1024;
constexpr int E_   = 2048;
constexpr int H_   = 32;
constexpr int KV_  = 8;
constexpr int HD_  = 64;
constexpr int G_   = H_ / KV_;        // 4
constexpr int CTX_ = P_ + S_;         // 2048
constexpr int M_   = B_ * S_;         // 2048 rows of tokens

// ---------------------------------------------------------------------------
// Scratch (static device allocations are the sanctioned workaround)
// ---------------------------------------------------------------------------
__device__ float    g_Q[(size_t)M_ * E_];                   // fp32 Q (pre-rope)
__device__ float    g_K[(size_t)M_ * KV_ * HD_];            // fp32 new K (pre-rope)
__device__ float    g_V[(size_t)M_ * KV_ * HD_];            // fp32 new V
__device__ uint32_t g_X16[(size_t)M_ * E_ / 2];             // x fp16 plane
__device__ uint32_t g_A16[(size_t)M_ * E_ / 2];             // attn out fp16 plane
__device__ uint32_t g_Wq16[(size_t)E_ * E_ / 2];            // fp16 packed weights
__device__ uint32_t g_Wk16[(size_t)KV_ * HD_ * E_ / 2];
__device__ uint32_t g_Wv16[(size_t)KV_ * HD_ * E_ / 2];
__device__ uint32_t g_Wo16[(size_t)E_ * E_ / 2];
__device__ uint32_t g_Q16[(size_t)M_ * H_ * 32];            // Q fp16 [row][h][hd/2]
__device__ uint32_t g_K16[(size_t)B_ * KV_ * CTX_ * 32];    // K fp16 [b][kv][t][hd/2]
__device__ uint32_t g_Vt16[(size_t)B_ * KV_ * HD_ * (CTX_/2)]; // V^T fp16 [b][kv][hd][t/2]

// ---------------------------------------------------------------------------
// fp16 helpers
// ---------------------------------------------------------------------------
__device__ __forceinline__ uint32_t h2pack(float a, float b)
{
    __half2 h = __floats2half2_rn(a, b);
    return *reinterpret_cast<uint32_t*>(&h);
}

__device__ __forceinline__ void mma_f16(float c[4],
    uint32_t a0, uint32_t a1, uint32_t a2, uint32_t a3,
    uint32_t b0, uint32_t b1)
{
    asm volatile(
        "mma.sync.aligned.m16n8k16.row.col.f32.f16.f16.f32 "
        "{%0,%1,%2,%3}, {%4,%5,%6,%7}, {%8,%9}, {%0,%1,%2,%3};"
        : "+f"(c[0]), "+f"(c[1]), "+f"(c[2]), "+f"(c[3])
        : "r"(a0), "r"(a1), "r"(a2), "r"(a3), "r"(b0), "r"(b1));
}

__device__ __forceinline__ void cp16(void* smem_dst, const void* gsrc)
{
    uint32_t d = (uint32_t)__cvta_generic_to_shared(smem_dst);
    asm volatile("cp.async.cg.shared.global [%0], [%1], 16;" :: "r"(d), "l"(gsrc));
}

// ---------------------------------------------------------------------------
// prep_all: single launch converting x and all weights to fp16 planes.
// grid (8192, 5): y=0 -> x, y=1 -> Wq, y=2 -> Wk, y=3 -> Wv, y=4 -> Wo.
// ---------------------------------------------------------------------------
__global__ void prep_all(const float* __restrict__ x,
                         const float* __restrict__ Wq, const float* __restrict__ Wk,
                         const float* __restrict__ Wv, const float* __restrict__ Wo)
{
    const int i = blockIdx.x * blockDim.x + threadIdx.x;
    const int y = blockIdx.y;
    if (y == 0) {
        float2 f = *(const float2*)(x + 2 * i);
        g_X16[i] = h2pack(f.x, f.y);
    } else if (y == 1) {
        float2 f = *(const float2*)(Wq + 2 * i);
        g_Wq16[i] = h2pack(f.x, f.y);
    } else if (y == 2) {
        if (i < KV_ * HD_ * E_ / 2) {
            float2 f = *(const float2*)(Wk + 2 * i);
            g_Wk16[i] = h2pack(f.x, f.y);
        }
    } else if (y == 3) {
        if (i < KV_ * HD_ * E_ / 2) {
            float2 f = *(const float2*)(Wv + 2 * i);
            g_Wv16[i] = h2pack(f.x, f.y);
        }
    } else {
        float2 f = *(const float2*)(Wo + 2 * i);
        g_Wo16[i] = h2pack(f.x, f.y);
    }
}

// ---------------------------------------------------------------------------
// Plain fp16 GEMM:  C[m][n] = sum_k A[m][k] * W[n][k]
// 128x128 tile, BK=32, 256 threads, 8 warps (2x4), warp tile 64x32.
// 3-stage cp.async pipeline, ONE __syncthreads per stage.
// ---------------------------------------------------------------------------
constexpr int GSTR2 = 20;             // plane stride in uint32 (16 used + 4 pad)
constexpr int PST   = 128 * GSTR2;    // uint32 per plane stage (10240 B)
constexpr int GSM2  = 3 * 2 * PST * 4;   // 61440 B

__device__ __forceinline__ void gemm2_stage(
    const uint32_t* __restrict__ A, const uint32_t* __restrict__ Bh,
    int Kp, int bm, int bn, int kp0, uint32_t* Ad, uint32_t* Bd, int tid)
{
#pragma unroll
    for (int i = 0; i < 2; i++) {
        int c = tid * 2 + i;                 // 0..511
        int row = c >> 2, off = (c & 3) * 4;
        cp16(Ad + row * GSTR2 + off, A  + (size_t)(bm + row) * Kp + kp0 + off);
        cp16(Bd + row * GSTR2 + off, Bh + (size_t)(bn + row) * Kp + kp0 + off);
    }
    asm volatile("cp.async.commit_group;" ::: "memory");
}

__device__ __forceinline__ void gemm2_core(
    const uint32_t* __restrict__ A, const uint32_t* __restrict__ Bh,
    float* __restrict__ C, int N, int K, int bm, int bn, char* smraw)
{
    uint32_t* As = (uint32_t*)smraw;
    uint32_t* Bs = (uint32_t*)(smraw + 3 * PST * 4);
    const int tid  = threadIdx.x;
    const int warp = tid >> 5;
    const int lane = tid & 31;
    const int g    = lane >> 2;
    const int tg   = lane & 3;
    const int wm   = (warp >> 2) * 64;
    const int wn   = (warp & 3) * 32;
    const int Kp   = K / 2;

    float acc[4][4][4];
#pragma unroll
    for (int i = 0; i < 4; i++)
#pragma unroll
        for (int j = 0; j < 4; j++)
#pragma unroll
            for (int r = 0; r < 4; r++) acc[i][j][r] = 0.f;

    const int nst = K / 32;    // 64
    gemm2_stage(A, Bh, Kp, bm, bn, 0,  As,       Bs,       tid);
    gemm2_stage(A, Bh, Kp, bm, bn, 16, As + PST, Bs + PST, tid);

    int buf = 0;               // s % 3
    for (int s = 0; s < nst; s++) {
        if (s + 1 < nst)
            asm volatile("cp.async.wait_group 1;" ::: "memory");
        else
            asm volatile("cp.async.wait_group 0;" ::: "memory");
        __syncthreads();

        // stage s+2 into buffer (s+2)%3 — its last readers were pre-sync
        if (s + 2 < nst) {
            int nb = buf + 2; if (nb >= 3) nb -= 3;
            gemm2_stage(A, Bh, Kp, bm, bn, (s + 2) * 16,
                        As + nb * PST, Bs + nb * PST, tid);
        }

        const uint32_t* Ab = As + buf * PST;
        const uint32_t* Bb = Bs + buf * PST;

#pragma unroll
        for (int ks = 0; ks < 2; ks++) {
            const int kp = ks * 8;
            uint32_t ta[4][4];
#pragma unroll
            for (int mt = 0; mt < 4; mt++) {
                const int rb = wm + mt * 16;
                ta[mt][0] = Ab[(rb + g)     * GSTR2 + kp + tg];
                ta[mt][1] = Ab[(rb + g + 8) * GSTR2 + kp + tg];
                ta[mt][2] = Ab[(rb + g)     * GSTR2 + kp + tg + 4];
                ta[mt][3] = Ab[(rb + g + 8) * GSTR2 + kp + tg + 4];
            }
            uint32_t tb[4][2];
#pragma unroll
            for (int nt = 0; nt < 4; nt++) {
                const int cb = wn + nt * 8;
                tb[nt][0] = Bb[(cb + g) * GSTR2 + kp + tg];
                tb[nt][1] = Bb[(cb + g) * GSTR2 + kp + tg + 4];
            }
#pragma unroll
            for (int mt = 0; mt < 4; mt++) {
#pragma unroll
                for (int nt = 0; nt < 4; nt++) {
                    mma_f16(acc[mt][nt],
                            ta[mt][0], ta[mt][1], ta[mt][2], ta[mt][3],
                            tb[nt][0], tb[nt][1]);
                }
            }
        }
        if (++buf == 3) buf = 0;
    }

    // epilogue
#pragma unroll
    for (int mt = 0; mt < 4; mt++) {
#pragma unroll
        for (int nt = 0; nt < 4; nt++) {
            const int row0 = bm + wm + mt * 16 + g;
            const int col  = bn + wn + nt * 8 + 2 * tg;
            *(float2*)&C[(size_t)row0 * N + col] =
                make_float2(acc[mt][nt][0], acc[mt][nt][1]);
            *(float2*)&C[(size_t)(row0 + 8) * N + col] =
                make_float2(acc[mt][nt][2], acc[mt][nt][3]);
        }
    }
}

// Fused Q+K+V projection: grid (24, 16). bx<16: Q; 16-19: K; 20-23: V.
__global__ __launch_bounds__(256, 2) void gemm_qkv()
{
    extern __shared__ char smraw[];
    const int bx = blockIdx.x, bm = blockIdx.y * 128;
    if (bx < 16)
        gemm2_core(g_X16, g_Wq16, g_Q, E_, E_, bm, bx * 128, smraw);
    else if (bx < 20)
        gemm2_core(g_X16, g_Wk16, g_K, KV_ * HD_, E_, bm, (bx - 16) * 128, smraw);
    else
        gemm2_core(g_X16, g_Wv16, g_V, KV_ * HD_, E_, bm, (bx - 20) * 128, smraw);
}

__global__ __launch_bounds__(256, 2) void gemm_o(float* __restrict__ out)
{
    extern __shared__ char smraw[];
    gemm2_core(g_A16, g_Wo16, out, E_, E_, blockIdx.y * 128, blockIdx.x * 128, smraw);
}

// ---------------------------------------------------------------------------
// RoPE + fp16 convert: Q -> single plane, new K -> single plane.
// ---------------------------------------------------------------------------
__global__ void rope_split_kernel(const float* __restrict__ cosp,
                                  const float* __restrict__ sinp)
{
    int idx = blockIdx.x * blockDim.x + threadIdx.x;
    constexpr int NH = H_ + KV_;                 // 40
    if (idx >= M_ * NH * 16) return;
    const int p    = idx & 15;
    const int item = idx >> 4;
    const int hh   = item % NH;
    const int row  = item / NH;                  // b*S + s

    const float* cb = cosp + (size_t)row * HD_;
    const float* sb = sinp + (size_t)row * HD_;
    const float c1a = cb[2*p],      c1b = cb[2*p+1];
    const float s1a = sb[2*p],      s1b = sb[2*p+1];
    const float c2a = cb[2*p+32],   c2b = cb[2*p+33];
    const float s2a = sb[2*p+32],   s2b = sb[2*p+33];

    const float* base;
    uint32_t* dst;
    if (hh < H_) {
        base = g_Q + (size_t)row * E_ + hh * HD_;
        dst  = g_Q16 + ((size_t)row * H_ + hh) * 32;
    } else {
        const int kvh = hh - H_;
        base = g_K + (size_t)row * (KV_ * HD_) + kvh * HD_;
        const int b = row / S_, s = row % S_;
        dst  = g_K16 + ((size_t)(b * KV_ + kvh) * CTX_ + P_ + s) * 32;
    }
    const float t1a = base[2*p],    t1b = base[2*p+1];
    const float t2a = base[2*p+32], t2b = base[2*p+33];
    dst[p]      = h2pack(t1a * c1a - t2a * s1a, t1b * c1b - t2b * s1b);
    dst[p + 16] = h2pack(t2a * c2a + t1a * s2a, t2b * c2b + t1b * s2b);
}

// ---------------------------------------------------------------------------
// prep_kv: cached K -> fp16 plane; all V -> fp16 transposed plane.
// ---------------------------------------------------------------------------
__global__ __launch_bounds__(256) void prep_kv(
    const float* __restrict__ cache_k, const float* __restrict__ cache_v)
{
    __shared__ float Vs[64][68];
    const int t0 = blockIdx.x * 64;
    const int kv = blockIdx.y, b = blockIdx.z;
    const int tid = threadIdx.x;
    const int row = tid >> 2, q = tid & 3;
    const int t = t0 + row;

    if (t < P_) {
        const float* src = cache_k + ((size_t)(b * KV_ + kv) * CTX_ + t) * HD_ + q * 16;
        uint32_t* dst = g_K16 + ((size_t)(b * KV_ + kv) * CTX_ + t) * 32 + q * 8;
#pragma unroll
        for (int i = 0; i < 4; i++) {
            float4 f = ((const float4*)src)[i];
            dst[2 * i + 0] = h2pack(f.x, f.y);
            dst[2 * i + 1] = h2pack(f.z, f.w);
        }
    }

    const float* vsrc;
    if (t < P_)
        vsrc = cache_v + ((size_t)(b * KV_ + kv) * CTX_ + t) * HD_;
    else
        vsrc = g_V + (size_t)(b * S_ + (t - P_)) * (KV_ * HD_) + kv * HD_;
#pragma unroll
    for (int i = 0; i < 4; i++)
        *(float4*)&Vs[row][q * 16 + 4 * i] = ((const float4*)(vsrc + q * 16))[i];
    __syncthreads();

    const int hd = tid >> 2, c = tid & 3;
    uint32_t* vdst = g_Vt16 + ((size_t)(b * KV_ + kv) * HD_ + hd) * (CTX_ / 2)
                   + t0 / 2 + c * 8;
#pragma unroll
    for (int i = 0; i < 8; i++) {
        const int tp = c * 8 + i;
        vdst[i] = h2pack(Vs[2 * tp][hd], Vs[2 * tp + 1][hd]);
    }
}

// ---------------------------------------------------------------------------
// Flash attention (pure fp16 QK and PV, fp32 accum), BLOCK_M=128, 8 warps.
// Grid (S/128, H, B), 256 threads; double-buffered cp.async K/V tiles.
// ---------------------------------------------------------------------------
constexpr int KT = 64 * 36;   // uint32 per K or V tile (stride 36, 32 used)

__global__ __launch_bounds__(256, 2) void attn_mma()
{
    __shared__ uint32_t KsS[2][KT];
    __shared__ uint32_t VtS[2][KT];

    // longest blocks (largest m0) first
    const int mblk = (int)gridDim.x - 1 - (int)blockIdx.x;
    const int m0 = mblk * 128;
    const int h  = blockIdx.y;
    const int b  = blockIdx.z;
    const int kv = h / G_;
    const int tid  = threadIdx.x;
    const int warp = tid >> 5;
    const int lane = tid & 31;
    const int g    = lane >> 2;
    const int tg   = lane & 3;

    const uint32_t* kplane = g_K16 + (size_t)(b * KV_ + kv) * CTX_ * 32;
    const uint32_t* vplane = g_Vt16 + (size_t)(b * KV_ + kv) * HD_ * (CTX_ / 2);
    const int ntile = (P_ + m0 + 128) / 64;

    // tile 0 loads
    {
#pragma unroll
        for (int i = 0; i < 2; i++) {
            const int sg = tid + i * 256;
            const int row = sg >> 3, off = (sg & 7) * 4;
            cp16(&KsS[0][row * 36 + off], kplane + (size_t)row * 32 + off);
            cp16(&VtS[0][row * 36 + off], vplane + (size_t)row * (CTX_ / 2) + off);
        }
        asm volatile("cp.async.commit_group;");
    }

    // Q fragments (single fp16 plane), persist across tiles
    uint32_t qf[4][4];
    {
        const uint32_t* q0 = g_Q16 + ((size_t)(b * S_ + m0 + warp * 16 + g)     * H_ + h) * 32;
        const uint32_t* q8 = g_Q16 + ((size_t)(b * S_ + m0 + warp * 16 + g + 8) * H_ + h) * 32;
#pragma unroll
        for (int ks = 0; ks < 4; ks++) {
            qf[ks][0] = q0[tg + 8 * ks];
            qf[ks][1] = q8[tg + 8 * ks];
            qf[ks][2] = q0[tg + 4 + 8 * ks];
            qf[ks][3] = q8[tg + 4 + 8 * ks];
        }
    }

    float o[8][4];
#pragma unroll
    for (int nt = 0; nt < 8; nt++)
#pragma unroll
        for (int r = 0; r < 4; r++) o[nt][r] = 0.f;
    float m0s = -1e30f, m1s = -1e30f, l0 = 0.f, l1 = 0.f;

    const int qpos0 = P_ + m0 + warp * 16 + g;
    const int wmax  = P_ + m0 + warp * 16 + 15;

    for (int it = 0; it < ntile; ++it) {
        const int t0 = it * 64;
        const int buf = it & 1;

        if (it + 1 < ntile) {
            const int nb = (it + 1) & 1;
#pragma unroll
            for (int i = 0; i < 2; i++) {
                const int sg = tid + i * 256;
                const int row = sg >> 3, off = (sg & 7) * 4;
                cp16(&KsS[nb][row * 36 + off],
                     kplane + (size_t)(t0 + 64 + row) * 32 + off);
                cp16(&VtS[nb][row * 36 + off],
                     vplane + (size_t)row * (CTX_ / 2) + (t0 + 64) / 2 + off);
            }
            asm volatile("cp.async.commit_group;");
            asm volatile("cp.async.wait_group 1;");
        } else {
            asm volatile("cp.async.wait_group 0;");
        }
        __syncthreads();

        if (t0 <= wmax) {
            const uint32_t* KsC = KsS[buf];
            const uint32_t* VtC = VtS[buf];

            // --- scores S = Q K^T (single fp16 mma per (ks, nt)) ---
            float s[8][4];
#pragma unroll
            for (int nt = 0; nt < 8; nt++)
#pragma unroll
                for (int r = 0; r < 4; r++) s[nt][r] = 0.f;

#pragma unroll
            for (int ks = 0; ks < 4; ks++) {
#pragma unroll
                for (int nt = 0; nt < 8; nt++) {
                    const uint32_t* kb = &KsC[(8 * nt + g) * 36 + 8 * ks + tg];
                    mma_f16(s[nt], qf[ks][0], qf[ks][1], qf[ks][2], qf[ks][3],
                            kb[0], kb[4]);
                }
            }

            // --- scale + causal mask ---
            const bool need_mask = (t0 + 63 > P_ + m0 + warp * 16);
            if (need_mask) {
#pragma unroll
                for (int nt = 0; nt < 8; nt++) {
                    const int col = t0 + 8 * nt + 2 * tg;
#pragma unroll
                    for (int r = 0; r < 4; r++) {
                        const int c  = col + (r & 1);
                        const int qp = (r < 2) ? qpos0 : qpos0 + 8;
                        s[nt][r] = (c > qp) ? -1e30f : s[nt][r] * 0.125f;
                    }
                }
            } else {
#pragma unroll
                for (int nt = 0; nt < 8; nt++)
#pragma unroll
                    for (int r = 0; r < 4; r++) s[nt][r] *= 0.125f;
            }

            // --- online softmax ---
            float mx0 = -1e30f, mx1 = -1e30f;
#pragma unroll
            for (int nt = 0; nt < 8; nt++) {
                mx0 = fmaxf(mx0, fmaxf(s[nt][0], s[nt][1]));
                mx1 = fmaxf(mx1, fmaxf(s[nt][2], s[nt][3]));
            }
            mx0 = fmaxf(mx0, __shfl_xor_sync(0xffffffffu, mx0, 1));
            mx0 = fmaxf(mx0, __shfl_xor_sync(0xffffffffu, mx0, 2));
            mx1 = fmaxf(mx1, __shfl_xor_sync(0xffffffffu, mx1, 1));
            mx1 = fmaxf(mx1, __shfl_xor_sync(0xffffffffu, mx1, 2));

            const float mn0 = fmaxf(m0s, mx0);
            const float mn1 = fmaxf(m1s, mx1);
            const float alpha0 = __expf(m0s - mn0);
            const float alpha1 = __expf(m1s - mn1);
            m0s = mn0; m1s = mn1;

            float sum0 = 0.f, sum1 = 0.f;
#pragma unroll
            for (int nt = 0; nt < 8; nt++) {
                s[nt][0] = __expf(s[nt][0] - mn0);
                s[nt][1] = __expf(s[nt][1] - mn0);
                s[nt][2] = __expf(s[nt][2] - mn1);
                s[nt][3] = __expf(s[nt][3] - mn1);
                sum0 += s[nt][0] + s[nt][1];
                sum1 += s[nt][2] + s[nt][3];
            }
            sum0 += __shfl_xor_sync(0xffffffffu, sum0, 1);
            sum0 += __shfl_xor_sync(0xffffffffu, sum0, 2);
            sum1 += __shfl_xor_sync(0xffffffffu, sum1, 1);
            sum1 += __shfl_xor_sync(0xffffffffu, sum1, 2);
            l0 = l0 * alpha0 + sum0;
            l1 = l1 * alpha1 + sum1;

#pragma unroll
            for (int nt = 0; nt < 8; nt++) {
                o[nt][0] *= alpha0; o[nt][1] *= alpha0;
                o[nt][2] *= alpha1; o[nt][3] *= alpha1;
            }

            // --- O += P V (single-fp16 P: 1 mma per (ks, nt)) ---
#pragma unroll
            for (int ks = 0; ks < 4; ks++) {
                uint32_t a0 = h2pack(s[2 * ks][0],     s[2 * ks][1]);
                uint32_t a1 = h2pack(s[2 * ks][2],     s[2 * ks][3]);
                uint32_t a2 = h2pack(s[2 * ks + 1][0], s[2 * ks + 1][1]);
                uint32_t a3 = h2pack(s[2 * ks + 1][2], s[2 * ks + 1][3]);
#pragma unroll
                for (int nt = 0; nt < 8; nt++) {
                    const uint32_t* vb = &VtC[(8 * nt + g) * 36 + 8 * ks + tg];
                    mma_f16(o[nt], a0, a1, a2, a3, vb[0], vb[4]);
                }
            }
        }

        __syncthreads();
    }

    // --- epilogue: write fp16 plane for the O projection ---
    const float inv0 = 1.f / l0;
    const float inv1 = 1.f / l1;
    const size_t row0  = (size_t)(b * S_ + m0 + warp * 16 + g);
    const size_t base0 = row0 * (E_ / 2) + h * (HD_ / 2) + tg;
    const size_t base8 = base0 + 4 * E_;     // +8 rows (8 * E/2)
#pragma unroll
    for (int nt = 0; nt < 8; nt++) {
        g_A16[base0 + 4 * nt] = h2pack(o[nt][0] * inv0, o[nt][1] * inv0);
        g_A16[base8 + 4 * nt] = h2pack(o[nt][2] * inv1, o[nt][3] * inv1);
    }
}

// ---------------------------------------------------------------------------
// Launcher
// ---------------------------------------------------------------------------
extern "C" void kernel_launch(void* const* d_in, const int* in_sizes, int n_in,
                              void* d_out, int out_size)
{
    const float* x       = (const float*)d_in[0];
    const float* cosp    = (const float*)d_in[1];
    const float* sinp    = (const float*)d_in[2];
    // d_in[3] = mask (causal; computed analytically)
    const float* cache_k = (const float*)d_in[4];
    const float* cache_v = (const float*)d_in[5];
    const float* Wq      = (const float*)d_in[6];
    const float* Wk      = (const float*)d_in[7];
    const float* Wv      = (const float*)d_in[8];
    const float* Wo      = (const float*)d_in[9];
    float* out           = (float*)d_out;

    cudaFuncSetAttribute(gemm_qkv, cudaFuncAttributeMaxDynamicSharedMemorySize, GSM2);
    cudaFuncSetAttribute(gemm_o,   cudaFuncAttributeMaxDynamicSharedMemorySize, GSM2);

    // 0) fp16 planes: x + weights (one launch)
    prep_all<<<dim3(M_ * E_ / 2 / 256, 5), 256>>>(x, Wq, Wk, Wv, Wo);

    // 1) fused Q/K/V projections (plain fp16 tensor cores, 3-stage pipeline)
    gemm_qkv<<<dim3(24, M_ / 128), 256, GSM2>>>();

    // 2) RoPE + fp16 convert of Q and new K
    {
        const int total = M_ * (H_ + KV_) * 16;
        rope_split_kernel<<<(total + 255) / 256, 256>>>(cosp, sinp);
    }

    // 3) cached K + all V into fp16 planes (V transposed)
    prep_kv<<<dim3(CTX_ / 64, KV_, B_), 256>>>(cache_k, cache_v);

    // 4) flash attention (pure fp16 mma, BLOCK_M=128)
    attn_mma<<<dim3(S_ / 128, H_, B_), 256>>>();

    // 5) output projection (plain fp16, 3-stage pipeline)
    gemm_o<<<dim3(16, 16), 256, GSM2>>>(out);
}

// round 12
// speedup vs baseline: 1.6304x; 1.0250x over previous
#include <cuda_runtime.h>
#include <cuda_fp16.h>
#include <math.h>
#include <stdint.h>

// ---------------------------------------------------------------------------
// Problem constants (LlamaAttention: B=2,S=1024,P=1024,E=2048,H=32,KV=8,HD=64)
// ---------------------------------------------------------------------------
constexpr int B_   = 2;
constexpr int S_   = 1024;
constexpr int P_   = 1024;
constexpr int E_   = 2048;
constexpr int H_   = 32;
constexpr int KV_  = 8;
constexpr int HD_  = 64;
constexpr int G_   = H_ / KV_;        // 4
constexpr int CTX_ = P_ + S_;         // 2048
constexpr int M_   = B_ * S_;         // 2048 rows of tokens

// ---------------------------------------------------------------------------
// Scratch (static device allocations are the sanctioned workaround)
// ---------------------------------------------------------------------------
__device__ float    g_Q[(size_t)M_ * E_];                   // fp32 Q (pre-rope)
__device__ float    g_K[(size_t)M_ * KV_ * HD_];            // fp32 new K (pre-rope)
__device__ float    g_V[(size_t)M_ * KV_ * HD_];            // fp32 new V
__device__ uint32_t g_X16[(size_t)M_ * E_ / 2];             // x fp16 plane
__device__ uint32_t g_A16[(size_t)M_ * E_ / 2];             // attn out fp16 plane
__device__ uint32_t g_Wq16[(size_t)E_ * E_ / 2];            // fp16 packed weights
__device__ uint32_t g_Wk16[(size_t)KV_ * HD_ * E_ / 2];
__device__ uint32_t g_Wv16[(size_t)KV_ * HD_ * E_ / 2];
__device__ uint32_t g_Wo16[(size_t)E_ * E_ / 2];
__device__ uint32_t g_Q16[(size_t)M_ * H_ * 32];            // Q fp16 [row][h][hd/2]
__device__ uint32_t g_K16[(size_t)B_ * KV_ * CTX_ * 32];    // K fp16 [b][kv][t][hd/2]
__device__ uint32_t g_Vt16[(size_t)B_ * KV_ * HD_ * (CTX_/2)]; // V^T fp16 [b][kv][hd][t/2]

// ---------------------------------------------------------------------------
// fp16 helpers
// ---------------------------------------------------------------------------
__device__ __forceinline__ uint32_t h2pack(float a, float b)
{
    __half2 h = __floats2half2_rn(a, b);
    return *reinterpret_cast<uint32_t*>(&h);
}

__device__ __forceinline__ void mma_f16(float c[4],
    uint32_t a0, uint32_t a1, uint32_t a2, uint32_t a3,
    uint32_t b0, uint32_t b1)
{
    asm volatile(
        "mma.sync.aligned.m16n8k16.row.col.f32.f16.f16.f32 "
        "{%0,%1,%2,%3}, {%4,%5,%6,%7}, {%8,%9}, {%0,%1,%2,%3};"
        : "+f"(c[0]), "+f"(c[1]), "+f"(c[2]), "+f"(c[3])
        : "r"(a0), "r"(a1), "r"(a2), "r"(a3), "r"(b0), "r"(b1));
}

__device__ __forceinline__ void cp16(void* smem_dst, const void* gsrc)
{
    uint32_t d = (uint32_t)__cvta_generic_to_shared(smem_dst);
    asm volatile("cp.async.cg.shared.global [%0], [%1], 16;" :: "r"(d), "l"(gsrc));
}

// ---------------------------------------------------------------------------
// prep_all: single launch converting x and all weights to fp16 planes.
// grid (8192, 5): y=0 -> x, y=1 -> Wq, y=2 -> Wk, y=3 -> Wv, y=4 -> Wo.
// ---------------------------------------------------------------------------
__global__ void prep_all(const float* __restrict__ x,
                         const float* __restrict__ Wq, const float* __restrict__ Wk,
                         const float* __restrict__ Wv, const float* __restrict__ Wo)
{
    const int i = blockIdx.x * blockDim.x + threadIdx.x;
    const int y = blockIdx.y;
    if (y == 0) {
        float2 f = *(const float2*)(x + 2 * i);
        g_X16[i] = h2pack(f.x, f.y);
    } else if (y == 1) {
        float2 f = *(const float2*)(Wq + 2 * i);
        g_Wq16[i] = h2pack(f.x, f.y);
    } else if (y == 2) {
        if (i < KV_ * HD_ * E_ / 2) {
            float2 f = *(const float2*)(Wk + 2 * i);
            g_Wk16[i] = h2pack(f.x, f.y);
        }
    } else if (y == 3) {
        if (i < KV_ * HD_ * E_ / 2) {
            float2 f = *(const float2*)(Wv + 2 * i);
            g_Wv16[i] = h2pack(f.x, f.y);
        }
    } else {
        float2 f = *(const float2*)(Wo + 2 * i);
        g_Wo16[i] = h2pack(f.x, f.y);
    }
}

// ---------------------------------------------------------------------------
// Plain fp16 GEMM core:  C[m][n] = sum_k A[m][k] * W[n][k]
// 128x128 tile, BK=32, 256 threads, 8 warps (2x4), warp tile 64x32.
// 3-stage cp.async pipeline, ONE __syncthreads per stage.
// ---------------------------------------------------------------------------
constexpr int GSTR2 = 20;             // plane stride in uint32 (16 used + 4 pad)
constexpr int PST   = 128 * GSTR2;    // uint32 per plane stage (10240 B)
constexpr int GSM2  = 3 * 2 * PST * 4;   // 61440 B

__device__ __forceinline__ void gemm2_stage(
    const uint32_t* __restrict__ A, const uint32_t* __restrict__ Bh,
    int Kp, int bm, int bn, int kp0, uint32_t* Ad, uint32_t* Bd, int tid)
{
#pragma unroll
    for (int i = 0; i < 2; i++) {
        int c = tid * 2 + i;                 // 0..511
        int row = c >> 2, off = (c & 3) * 4;
        cp16(Ad + row * GSTR2 + off, A  + (size_t)(bm + row) * Kp + kp0 + off);
        cp16(Bd + row * GSTR2 + off, Bh + (size_t)(bn + row) * Kp + kp0 + off);
    }
    asm volatile("cp.async.commit_group;" ::: "memory");
}

__device__ __forceinline__ void gemm2_core(
    const uint32_t* __restrict__ A, const uint32_t* __restrict__ Bh,
    float* __restrict__ C, int N, int K, int bm, int bn, char* smraw)
{
    uint32_t* As = (uint32_t*)smraw;
    uint32_t* Bs = (uint32_t*)(smraw + 3 * PST * 4);
    const int tid  = threadIdx.x;
    const int warp = tid >> 5;
    const int lane = tid & 31;
    const int g    = lane >> 2;
    const int tg   = lane & 3;
    const int wm   = (warp >> 2) * 64;
    const int wn   = (warp & 3) * 32;
    const int Kp   = K / 2;

    float acc[4][4][4];
#pragma unroll
    for (int i = 0; i < 4; i++)
#pragma unroll
        for (int j = 0; j < 4; j++)
#pragma unroll
            for (int r = 0; r < 4; r++) acc[i][j][r] = 0.f;

    const int nst = K / 32;    // 64
    gemm2_stage(A, Bh, Kp, bm, bn, 0,  As,       Bs,       tid);
    gemm2_stage(A, Bh, Kp, bm, bn, 16, As + PST, Bs + PST, tid);

    int buf = 0;               // s % 3
    for (int s = 0; s < nst; s++) {
        if (s + 1 < nst)
            asm volatile("cp.async.wait_group 1;" ::: "memory");
        else
            asm volatile("cp.async.wait_group 0;" ::: "memory");
        __syncthreads();

        if (s + 2 < nst) {
            int nb = buf + 2; if (nb >= 3) nb -= 3;
            gemm2_stage(A, Bh, Kp, bm, bn, (s + 2) * 16,
                        As + nb * PST, Bs + nb * PST, tid);
        }

        const uint32_t* Ab = As + buf * PST;
        const uint32_t* Bb = Bs + buf * PST;

#pragma unroll
        for (int ks = 0; ks < 2; ks++) {
            const int kp = ks * 8;
            uint32_t ta[4][4];
#pragma unroll
            for (int mt = 0; mt < 4; mt++) {
                const int rb = wm + mt * 16;
                ta[mt][0] = Ab[(rb + g)     * GSTR2 + kp + tg];
                ta[mt][1] = Ab[(rb + g + 8) * GSTR2 + kp + tg];
                ta[mt][2] = Ab[(rb + g)     * GSTR2 + kp + tg + 4];
                ta[mt][3] = Ab[(rb + g + 8) * GSTR2 + kp + tg + 4];
            }
            uint32_t tb[4][2];
#pragma unroll
            for (int nt = 0; nt < 4; nt++) {
                const int cb = wn + nt * 8;
                tb[nt][0] = Bb[(cb + g) * GSTR2 + kp + tg];
                tb[nt][1] = Bb[(cb + g) * GSTR2 + kp + tg + 4];
            }
#pragma unroll
            for (int mt = 0; mt < 4; mt++) {
#pragma unroll
                for (int nt = 0; nt < 4; nt++) {
                    mma_f16(acc[mt][nt],
                            ta[mt][0], ta[mt][1], ta[mt][2], ta[mt][3],
                            tb[nt][0], tb[nt][1]);
                }
            }
        }
        if (++buf == 3) buf = 0;
    }

    // epilogue
#pragma unroll
    for (int mt = 0; mt < 4; mt++) {
#pragma unroll
        for (int nt = 0; nt < 4; nt++) {
            const int row0 = bm + wm + mt * 16 + g;
            const int col  = bn + wn + nt * 8 + 2 * tg;
            *(float2*)&C[(size_t)row0 * N + col] =
                make_float2(acc[mt][nt][0], acc[mt][nt][1]);
            *(float2*)&C[(size_t)(row0 + 8) * N + col] =
                make_float2(acc[mt][nt][2], acc[mt][nt][3]);
        }
    }
}

// ---------------------------------------------------------------------------
// KV-cache conversion body (t < P): K -> fp16 plane, V -> fp16 transposed.
// 256 threads; smem scratch carved from caller-provided buffer.
// ---------------------------------------------------------------------------
__device__ __forceinline__ void prep_cache_body(
    const float* __restrict__ cache_k, const float* __restrict__ cache_v,
    int t0, int kv, int b, char* smraw)
{
    float (*Vs)[68] = (float(*)[68])smraw;     // 64*68*4 = 17408 B < GSM2
    const int tid = threadIdx.x;
    const int row = tid >> 2, q = tid & 3;
    const int t = t0 + row;

    {
        const float* src = cache_k + ((size_t)(b * KV_ + kv) * CTX_ + t) * HD_ + q * 16;
        uint32_t* dst = g_K16 + ((size_t)(b * KV_ + kv) * CTX_ + t) * 32 + q * 8;
#pragma unroll
        for (int i = 0; i < 4; i++) {
            float4 f = ((const float4*)src)[i];
            dst[2 * i + 0] = h2pack(f.x, f.y);
            dst[2 * i + 1] = h2pack(f.z, f.w);
        }
    }

    const float* vsrc = cache_v + ((size_t)(b * KV_ + kv) * CTX_ + t) * HD_;
#pragma unroll
    for (int i = 0; i < 4; i++)
        *(float4*)&Vs[row][q * 16 + 4 * i] = ((const float4*)(vsrc + q * 16))[i];
    __syncthreads();

    const int hd = tid >> 2, c = tid & 3;
    uint32_t* vdst = g_Vt16 + ((size_t)(b * KV_ + kv) * HD_ + hd) * (CTX_ / 2)
                   + t0 / 2 + c * 8;
#pragma unroll
    for (int i = 0; i < 8; i++) {
        const int tp = c * 8 + i;
        vdst[i] = h2pack(Vs[2 * tp][hd], Vs[2 * tp + 1][hd]);
    }
}

// ---------------------------------------------------------------------------
// Fused Q+K+V projection + KV-cache prep tail.
// 1-D grid of 640 blocks: bid<384 -> GEMM (bx=bid%24, by=bid/24);
// bid>=384 -> cache conversion (256 blocks fill the GEMM's second wave).
// ---------------------------------------------------------------------------
__global__ __launch_bounds__(256, 2) void gemm_qkv_prep(
    const float* __restrict__ cache_k, const float* __restrict__ cache_v)
{
    extern __shared__ char smraw[];
    const int bid = blockIdx.x;
    if (bid < 384) {
        const int bx = bid % 24, bm = (bid / 24) * 128;
        if (bx < 16)
            gemm2_core(g_X16, g_Wq16, g_Q, E_, E_, bm, bx * 128, smraw);
        else if (bx < 20)
            gemm2_core(g_X16, g_Wk16, g_K, KV_ * HD_, E_, bm, (bx - 16) * 128, smraw);
        else
            gemm2_core(g_X16, g_Wv16, g_V, KV_ * HD_, E_, bm, (bx - 20) * 128, smraw);
    } else {
        const int pb = bid - 384;          // 0..255 (t < P only)
        const int t0 = (pb % 16) * 64;
        const int kv = (pb / 16) % 8;
        const int b  = pb / 128;
        prep_cache_body(cache_k, cache_v, t0, kv, b, smraw);
    }
}

__global__ __launch_bounds__(256, 2) void gemm_o(float* __restrict__ out)
{
    extern __shared__ char smraw[];
    gemm2_core(g_A16, g_Wo16, out, E_, E_, blockIdx.y * 128, blockIdx.x * 128, smraw);
}

// ---------------------------------------------------------------------------
// RoPE + fp16 convert: Q -> single plane, new K -> single plane.
// ---------------------------------------------------------------------------
__global__ void rope_split_kernel(const float* __restrict__ cosp,
                                  const float* __restrict__ sinp)
{
    int idx = blockIdx.x * blockDim.x + threadIdx.x;
    constexpr int NH = H_ + KV_;                 // 40
    if (idx >= M_ * NH * 16) return;
    const int p    = idx & 15;
    const int item = idx >> 4;
    const int hh   = item % NH;
    const int row  = item / NH;                  // b*S + s

    const float* cb = cosp + (size_t)row * HD_;
    const float* sb = sinp + (size_t)row * HD_;
    const float c1a = cb[2*p],      c1b = cb[2*p+1];
    const float s1a = sb[2*p],      s1b = sb[2*p+1];
    const float c2a = cb[2*p+32],   c2b = cb[2*p+33];
    const float s2a = sb[2*p+32],   s2b = sb[2*p+33];

    const float* base;
    uint32_t* dst;
    if (hh < H_) {
        base = g_Q + (size_t)row * E_ + hh * HD_;
        dst  = g_Q16 + ((size_t)row * H_ + hh) * 32;
    } else {
        const int kvh = hh - H_;
        base = g_K + (size_t)row * (KV_ * HD_) + kvh * HD_;
        const int b = row / S_, s = row % S_;
        dst  = g_K16 + ((size_t)(b * KV_ + kvh) * CTX_ + P_ + s) * 32;
    }
    const float t1a = base[2*p],    t1b = base[2*p+1];
    const float t2a = base[2*p+32], t2b = base[2*p+33];
    dst[p]      = h2pack(t1a * c1a - t2a * s1a, t1b * c1b - t2b * s1b);
    dst[p + 16] = h2pack(t2a * c2a + t1a * s2a, t2b * c2b + t1b * s2b);
}

// ---------------------------------------------------------------------------
// prep_new_v: new V rows (t >= P) from g_V -> fp16 transposed plane.
// Grid (S/64, KV, B), 256 threads.
// ---------------------------------------------------------------------------
__global__ __launch_bounds__(256) void prep_new_v()
{
    __shared__ float Vs[64][68];
    const int t0 = P_ + blockIdx.x * 64;
    const int kv = blockIdx.y, b = blockIdx.z;
    const int tid = threadIdx.x;
    const int row = tid >> 2, q = tid & 3;
    const int t = t0 + row;

    const float* vsrc = g_V + (size_t)(b * S_ + (t - P_)) * (KV_ * HD_) + kv * HD_;
#pragma unroll
    for (int i = 0; i < 4; i++)
        *(float4*)&Vs[row][q * 16 + 4 * i] = ((const float4*)(vsrc + q * 16))[i];
    __syncthreads();

    const int hd = tid >> 2, c = tid & 3;
    uint32_t* vdst = g_Vt16 + ((size_t)(b * KV_ + kv) * HD_ + hd) * (CTX_ / 2)
                   + t0 / 2 + c * 8;
#pragma unroll
    for (int i = 0; i < 8; i++) {
        const int tp = c * 8 + i;
        vdst[i] = h2pack(Vs[2 * tp][hd], Vs[2 * tp + 1][hd]);
    }
}

// ---------------------------------------------------------------------------
// Flash attention (pure fp16 QK and PV, fp32 accum), BLOCK_M=64, 4 warps.
// Grid (S/64, H, B), 128 threads, 4 blocks/SM for cross-block overlap.
// ---------------------------------------------------------------------------
constexpr int KT = 64 * 36;   // uint32 per K or V tile (stride 36, 32 used)

__global__ __launch_bounds__(128, 4) void attn_mma()
{
    __shared__ uint32_t KsS[2][KT];
    __shared__ uint32_t VtS[2][KT];

    // longest blocks (largest m0) first
    const int mblk = (int)gridDim.x - 1 - (int)blockIdx.x;
    const int m0 = mblk * 64;
    const int h  = blockIdx.y;
    const int b  = blockIdx.z;
    const int kv = h / G_;
    const int tid  = threadIdx.x;
    const int warp = tid >> 5;
    const int lane = tid & 31;
    const int g    = lane >> 2;
    const int tg   = lane & 3;

    const uint32_t* kplane = g_K16 + (size_t)(b * KV_ + kv) * CTX_ * 32;
    const uint32_t* vplane = g_Vt16 + (size_t)(b * KV_ + kv) * HD_ * (CTX_ / 2);
    const int ntile = (P_ + m0 + 64) / 64;

    // tile 0 loads: 512 16B-segments per tile over 128 threads (4 each)
    {
#pragma unroll
        for (int i = 0; i < 4; i++) {
            const int sg = tid + i * 128;
            const int row = sg >> 3, off = (sg & 7) * 4;
            cp16(&KsS[0][row * 36 + off], kplane + (size_t)row * 32 + off);
            cp16(&VtS[0][row * 36 + off], vplane + (size_t)row * (CTX_ / 2) + off);
        }
        asm volatile("cp.async.commit_group;");
    }

    // Q fragments (single fp16 plane), persist across tiles
    uint32_t qf[4][4];
    {
        const uint32_t* q0 = g_Q16 + ((size_t)(b * S_ + m0 + warp * 16 + g)     * H_ + h) * 32;
        const uint32_t* q8 = g_Q16 + ((size_t)(b * S_ + m0 + warp * 16 + g + 8) * H_ + h) * 32;
#pragma unroll
        for (int ks = 0; ks < 4; ks++) {
            qf[ks][0] = q0[tg + 8 * ks];
            qf[ks][1] = q8[tg + 8 * ks];
            qf[ks][2] = q0[tg + 4 + 8 * ks];
            qf[ks][3] = q8[tg + 4 + 8 * ks];
        }
    }

    float o[8][4];
#pragma unroll
    for (int nt = 0; nt < 8; nt++)
#pragma unroll
        for (int r = 0; r < 4; r++) o[nt][r] = 0.f;
    float m0s = -1e30f, m1s = -1e30f, l0 = 0.f, l1 = 0.f;

    const int qpos0 = P_ + m0 + warp * 16 + g;
    const int wmax  = P_ + m0 + warp * 16 + 15;

    for (int it = 0; it < ntile; ++it) {
        const int t0 = it * 64;
        const int buf = it & 1;

        if (it + 1 < ntile) {
            const int nb = (it + 1) & 1;
#pragma unroll
            for (int i = 0; i < 4; i++) {
                const int sg = tid + i * 128;
                const int row = sg >> 3, off = (sg & 7) * 4;
                cp16(&KsS[nb][row * 36 + off],
                     kplane + (size_t)(t0 + 64 + row) * 32 + off);
                cp16(&VtS[nb][row * 36 + off],
                     vplane + (size_t)row * (CTX_ / 2) + (t0 + 64) / 2 + off);
            }
            asm volatile("cp.async.commit_group;");
            asm volatile("cp.async.wait_group 1;");
        } else {
            asm volatile("cp.async.wait_group 0;");
        }
        __syncthreads();

        if (t0 <= wmax) {
            const uint32_t* KsC = KsS[buf];
            const uint32_t* VtC = VtS[buf];

            // --- scores S = Q K^T (single fp16 mma per (ks, nt)) ---
            float s[8][4];
#pragma unroll
            for (int nt = 0; nt < 8; nt++)
#pragma unroll
                for (int r = 0; r < 4; r++) s[nt][r] = 0.f;

#pragma unroll
            for (int ks = 0; ks < 4; ks++) {
#pragma unroll
                for (int nt = 0; nt < 8; nt++) {
                    const uint32_t* kb = &KsC[(8 * nt + g) * 36 + 8 * ks + tg];
                    mma_f16(s[nt], qf[ks][0], qf[ks][1], qf[ks][2], qf[ks][3],
                            kb[0], kb[4]);
                }
            }

            // --- scale + causal mask ---
            const bool need_mask = (t0 + 63 > P_ + m0 + warp * 16);
            if (need_mask) {
#pragma unroll
                for (int nt = 0; nt < 8; nt++) {
                    const int col = t0 + 8 * nt + 2 * tg;
#pragma unroll
                    for (int r = 0; r < 4; r++) {
                        const int c  = col + (r & 1);
                        const int qp = (r < 2) ? qpos0 : qpos0 + 8;
                        s[nt][r] = (c > qp) ? -1e30f : s[nt][r] * 0.125f;
                    }
                }
            } else {
#pragma unroll
                for (int nt = 0; nt < 8; nt++)
#pragma unroll
                    for (int r = 0; r < 4; r++) s[nt][r] *= 0.125f;
            }

            // --- online softmax ---
            float mx0 = -1e30f, mx1 = -1e30f;
#pragma unroll
            for (int nt = 0; nt < 8; nt++) {
                mx0 = fmaxf(mx0, fmaxf(s[nt][0], s[nt][1]));
                mx1 = fmaxf(mx1, fmaxf(s[nt][2], s[nt][3]));
            }
            mx0 = fmaxf(mx0, __shfl_xor_sync(0xffffffffu, mx0, 1));
            mx0 = fmaxf(mx0, __shfl_xor_sync(0xffffffffu, mx0, 2));
            mx1 = fmaxf(mx1, __shfl_xor_sync(0xffffffffu, mx1, 1));
            mx1 = fmaxf(mx1, __shfl_xor_sync(0xffffffffu, mx1, 2));

            const float mn0 = fmaxf(m0s, mx0);
            const float mn1 = fmaxf(m1s, mx1);
            const float alpha0 = __expf(m0s - mn0);
            const float alpha1 = __expf(m1s - mn1);
            m0s = mn0; m1s = mn1;

            float sum0 = 0.f, sum1 = 0.f;
#pragma unroll
            for (int nt = 0; nt < 8; nt++) {
                s[nt][0] = __expf(s[nt][0] - mn0);
                s[nt][1] = __expf(s[nt][1] - mn0);
                s[nt][2] = __expf(s[nt][2] - mn1);
                s[nt][3] = __expf(s[nt][3] - mn1);
                sum0 += s[nt][0] + s[nt][1];
                sum1 += s[nt][2] + s[nt][3];
            }
            sum0 += __shfl_xor_sync(0xffffffffu, sum0, 1);
            sum0 += __shfl_xor_sync(0xffffffffu, sum0, 2);
            sum1 += __shfl_xor_sync(0xffffffffu, sum1, 1);
            sum1 += __shfl_xor_sync(0xffffffffu, sum1, 2);
            l0 = l0 * alpha0 + sum0;
            l1 = l1 * alpha1 + sum1;

#pragma unroll
            for (int nt = 0; nt < 8; nt++) {
                o[nt][0] *= alpha0; o[nt][1] *= alpha0;
                o[nt][2] *= alpha1; o[nt][3] *= alpha1;
            }

            // --- O += P V (single-fp16 P: 1 mma per (ks, nt)) ---
#pragma unroll
            for (int ks = 0; ks < 4; ks++) {
                uint32_t a0 = h2pack(s[2 * ks][0],     s[2 * ks][1]);
                uint32_t a1 = h2pack(s[2 * ks][2],     s[2 * ks][3]);
                uint32_t a2 = h2pack(s[2 * ks + 1][0], s[2 * ks + 1][1]);
                uint32_t a3 = h2pack(s[2 * ks + 1][2], s[2 * ks + 1][3]);
#pragma unroll
                for (int nt = 0; nt < 8; nt++) {
                    const uint32_t* vb = &VtC[(8 * nt + g) * 36 + 8 * ks + tg];
                    mma_f16(o[nt], a0, a1, a2, a3, vb[0], vb[4]);
                }
            }
        }

        __syncthreads();
    }

    // --- epilogue: write fp16 plane for the O projection ---
    const float inv0 = 1.f / l0;
    const float inv1 = 1.f / l1;
    const size_t row0  = (size_t)(b * S_ + m0 + warp * 16 + g);
    const size_t base0 = row0 * (E_ / 2) + h * (HD_ / 2) + tg;
    const size_t base8 = base0 + 4 * E_;     // +8 rows (8 * E/2)
#pragma unroll
    for (int nt = 0; nt < 8; nt++) {
        g_A16[base0 + 4 * nt] = h2pack(o[nt][0] * inv0, o[nt][1] * inv0);
        g_A16[base8 + 4 * nt] = h2pack(o[nt][2] * inv1, o[nt][3] * inv1);
    }
}

// ---------------------------------------------------------------------------
// Launcher
// ---------------------------------------------------------------------------
extern "C" void kernel_launch(void* const* d_in, const int* in_sizes, int n_in,
                              void* d_out, int out_size)
{
    const float* x       = (const float*)d_in[0];
    const float* cosp    = (const float*)d_in[1];
    const float* sinp    = (const float*)d_in[2];
    // d_in[3] = mask (causal; computed analytically)
    const float* cache_k = (const float*)d_in[4];
    const float* cache_v = (const float*)d_in[5];
    const float* Wq      = (const float*)d_in[6];
    const float* Wk      = (const float*)d_in[7];
    const float* Wv      = (const float*)d_in[8];
    const float* Wo      = (const float*)d_in[9];
    float* out           = (float*)d_out;

    cudaFuncSetAttribute(gemm_qkv_prep, cudaFuncAttributeMaxDynamicSharedMemorySize, GSM2);
    cudaFuncSetAttribute(gemm_o,        cudaFuncAttributeMaxDynamicSharedMemorySize, GSM2);

    // 0) fp16 planes: x + weights (one launch)
    prep_all<<<dim3(M_ * E_ / 2 / 256, 5), 256>>>(x, Wq, Wk, Wv, Wo);

    // 1) fused Q/K/V projections + KV-cache conversion in the wave tail
    gemm_qkv_prep<<<640, 256, GSM2>>>(cache_k, cache_v);

    // 2) RoPE + fp16 convert of Q and new K
    {
        const int total = M_ * (H_ + KV_) * 16;
        rope_split_kernel<<<(total + 255) / 256, 256>>>(cosp, sinp);
    }

    // 3) new V rows -> transposed fp16 plane
    prep_new_v<<<dim3(S_ / 64, KV_, B_), 256>>>();

    // 4) flash attention (pure fp16 mma, BLOCK_M=64, 4 blocks/SM)
    attn_mma<<<dim3(S_ / 64, H_, B_), 128>>>();

    // 5) output projection (plain fp16, 3-stage pipeline)
    gemm_o<<<dim3(16, 16), 256, GSM2>>>(out);
}

// round 13
// speedup vs baseline: 1.7414x; 1.0680x over previous
#include <cuda_runtime.h>
#include <cuda_fp16.h>
#include <math.h>
#include <stdint.h>

// ---------------------------------------------------------------------------
// Problem constants (LlamaAttention: B=2,S=1024,P=1024,E=2048,H=32,KV=8,HD=64)
// ---------------------------------------------------------------------------
constexpr int B_   = 2;
constexpr int S_   = 1024;
constexpr int P_   = 1024;
constexpr int E_   = 2048;
constexpr int H_   = 32;
constexpr int KV_  = 8;
constexpr int HD_  = 64;
constexpr int G_   = H_ / KV_;        // 4
constexpr int CTX_ = P_ + S_;         // 2048
constexpr int M_   = B_ * S_;         // 2048 rows of tokens

// ---------------------------------------------------------------------------
// Scratch (static device allocations are the sanctioned workaround)
// ---------------------------------------------------------------------------
__device__ float    g_Q[(size_t)M_ * E_];                   // fp32 Q (pre-rope)
__device__ float    g_K[(size_t)M_ * KV_ * HD_];            // fp32 new K (pre-rope)
__device__ float    g_V[(size_t)M_ * KV_ * HD_];            // fp32 new V
__device__ uint32_t g_X16[(size_t)M_ * E_ / 2];             // x fp16 plane
__device__ uint32_t g_A16[(size_t)M_ * E_ / 2];             // attn out fp16 plane
__device__ uint32_t g_Wq16[(size_t)E_ * E_ / 2];            // fp16 packed weights
__device__ uint32_t g_Wk16[(size_t)KV_ * HD_ * E_ / 2];
__device__ uint32_t g_Wv16[(size_t)KV_ * HD_ * E_ / 2];
__device__ uint32_t g_Wo16[(size_t)E_ * E_ / 2];
__device__ uint32_t g_Q16[(size_t)M_ * H_ * 32];            // Q fp16 [row][h][hd/2]
__device__ uint32_t g_K16[(size_t)B_ * KV_ * CTX_ * 32];    // K fp16 [b][kv][t][hd/2]
__device__ uint32_t g_Vt16[(size_t)B_ * KV_ * HD_ * (CTX_/2)]; // V^T fp16 [b][kv][hd][t/2]

// ---------------------------------------------------------------------------
// fp16 helpers
// ---------------------------------------------------------------------------
__device__ __forceinline__ uint32_t h2pack(float a, float b)
{
    __half2 h = __floats2half2_rn(a, b);
    return *reinterpret_cast<uint32_t*>(&h);
}

__device__ __forceinline__ void mma_f16(float c[4],
    uint32_t a0, uint32_t a1, uint32_t a2, uint32_t a3,
    uint32_t b0, uint32_t b1)
{
    asm volatile(
        "mma.sync.aligned.m16n8k16.row.col.f32.f16.f16.f32 "
        "{%0,%1,%2,%3}, {%4,%5,%6,%7}, {%8,%9}, {%0,%1,%2,%3};"
        : "+f"(c[0]), "+f"(c[1]), "+f"(c[2]), "+f"(c[3])
        : "r"(a0), "r"(a1), "r"(a2), "r"(a3), "r"(b0), "r"(b1));
}

__device__ __forceinline__ void cp16(void* smem_dst, const void* gsrc)
{
    uint32_t d = (uint32_t)__cvta_generic_to_shared(smem_dst);
    asm volatile("cp.async.cg.shared.global [%0], [%1], 16;" :: "r"(d), "l"(gsrc));
}

__device__ __forceinline__ uint32_t sm_addr(const void* p)
{
    return (uint32_t)__cvta_generic_to_shared(p);
}

__device__ __forceinline__ void ldsm4(uint32_t& r0, uint32_t& r1,
                                      uint32_t& r2, uint32_t& r3, uint32_t addr)
{
    asm volatile("ldmatrix.sync.aligned.m8n8.x4.shared.b16 {%0,%1,%2,%3}, [%4];"
                 : "=r"(r0), "=r"(r1), "=r"(r2), "=r"(r3) : "r"(addr));
}

// ---------------------------------------------------------------------------
// prep_all: single launch converting x and all weights to fp16 planes.
// ---------------------------------------------------------------------------
__global__ void prep_all(const float* __restrict__ x,
                         const float* __restrict__ Wq, const float* __restrict__ Wk,
                         const float* __restrict__ Wv, const float* __restrict__ Wo)
{
    const int i = blockIdx.x * blockDim.x + threadIdx.x;
    const int y = blockIdx.y;
    if (y == 0) {
        float2 f = *(const float2*)(x + 2 * i);
        g_X16[i] = h2pack(f.x, f.y);
    } else if (y == 1) {
        float2 f = *(const float2*)(Wq + 2 * i);
        g_Wq16[i] = h2pack(f.x, f.y);
    } else if (y == 2) {
        if (i < KV_ * HD_ * E_ / 2) {
            float2 f = *(const float2*)(Wk + 2 * i);
            g_Wk16[i] = h2pack(f.x, f.y);
        }
    } else if (y == 3) {
        if (i < KV_ * HD_ * E_ / 2) {
            float2 f = *(const float2*)(Wv + 2 * i);
            g_Wv16[i] = h2pack(f.x, f.y);
        }
    } else {
        float2 f = *(const float2*)(Wo + 2 * i);
        g_Wo16[i] = h2pack(f.x, f.y);
    }
}

// ---------------------------------------------------------------------------
// Plain fp16 GEMM core:  C[m][n] = sum_k A[m][k] * W[n][k]
// 128x128 tile, BK=32, 256 threads, 8 warps (2x4), warp tile 64x32.
// 3-stage cp.async pipeline, ONE __syncthreads per stage, ldmatrix frags.
// ---------------------------------------------------------------------------
constexpr int GSTR2 = 20;             // plane stride in uint32 (16 used + 4 pad)
constexpr int PST   = 128 * GSTR2;    // uint32 per plane stage (10240 B)
constexpr int GSM2  = 3 * 2 * PST * 4;   // 61440 B

__device__ __forceinline__ void gemm2_stage(
    const uint32_t* __restrict__ A, const uint32_t* __restrict__ Bh,
    int Kp, int bm, int bn, int kp0, uint32_t* Ad, uint32_t* Bd, int tid)
{
#pragma unroll
    for (int i = 0; i < 2; i++) {
        int c = tid * 2 + i;                 // 0..511
        int row = c >> 2, off = (c & 3) * 4;
        cp16(Ad + row * GSTR2 + off, A  + (size_t)(bm + row) * Kp + kp0 + off);
        cp16(Bd + row * GSTR2 + off, Bh + (size_t)(bn + row) * Kp + kp0 + off);
    }
    asm volatile("cp.async.commit_group;" ::: "memory");
}

__device__ __forceinline__ void gemm2_core(
    const uint32_t* __restrict__ A, const uint32_t* __restrict__ Bh,
    float* __restrict__ C, int N, int K, int bm, int bn, char* smraw)
{
    uint32_t* As = (uint32_t*)smraw;
    uint32_t* Bs = (uint32_t*)(smraw + 3 * PST * 4);
    const int tid  = threadIdx.x;
    const int warp = tid >> 5;
    const int lane = tid & 31;
    const int g    = lane >> 2;
    const int tg   = lane & 3;
    const int wm   = (warp >> 2) * 64;
    const int wn   = (warp & 3) * 32;
    const int Kp   = K / 2;

    // ldmatrix lane addressing
    const int lA_row = (lane & 7) + ((lane >> 3) & 1) * 8;  // A quads: r0-7,k | r8-15,k | r0-7,k+4 | r8-15,k+4
    const int lA_col = ((lane >> 4) & 1) * 4;
    const int lB_row = (lane & 7) + ((lane >> 4) & 1) * 8;  // B quads: r0-7,k | r0-7,k+4 | r8-15,k | r8-15,k+4
    const int lB_col = ((lane >> 3) & 1) * 4;

    float acc[4][4][4];
#pragma unroll
    for (int i = 0; i < 4; i++)
#pragma unroll
        for (int j = 0; j < 4; j++)
#pragma unroll
            for (int r = 0; r < 4; r++) acc[i][j][r] = 0.f;

    const int nst = K / 32;    // 64
    gemm2_stage(A, Bh, Kp, bm, bn, 0,  As,       Bs,       tid);
    gemm2_stage(A, Bh, Kp, bm, bn, 16, As + PST, Bs + PST, tid);

    int buf = 0;               // s % 3
    for (int s = 0; s < nst; s++) {
        if (s + 1 < nst)
            asm volatile("cp.async.wait_group 1;" ::: "memory");
        else
            asm volatile("cp.async.wait_group 0;" ::: "memory");
        __syncthreads();

        if (s + 2 < nst) {
            int nb = buf + 2; if (nb >= 3) nb -= 3;
            gemm2_stage(A, Bh, Kp, bm, bn, (s + 2) * 16,
                        As + nb * PST, Bs + nb * PST, tid);
        }

        const uint32_t* Ab = As + buf * PST;
        const uint32_t* Bb = Bs + buf * PST;
        const uint32_t aBase = sm_addr(Ab + (wm + lA_row) * GSTR2 + lA_col);
        const uint32_t bBase = sm_addr(Bb + (wn + lB_row) * GSTR2 + lB_col);

#pragma unroll
        for (int ks = 0; ks < 2; ks++) {
            const uint32_t ko = ks * 32;   // 8 uint32 = 32 bytes
            uint32_t ta[4][4];
#pragma unroll
            for (int mt = 0; mt < 4; mt++)
                ldsm4(ta[mt][0], ta[mt][1], ta[mt][2], ta[mt][3],
                      aBase + mt * 16 * GSTR2 * 4 + ko);
            uint32_t tb[4][2];
#pragma unroll
            for (int np = 0; np < 2; np++)
                ldsm4(tb[2*np][0], tb[2*np][1], tb[2*np+1][0], tb[2*np+1][1],
                      bBase + np * 16 * GSTR2 * 4 + ko);
#pragma unroll
            for (int mt = 0; mt < 4; mt++) {
#pragma unroll
                for (int nt = 0; nt < 4; nt++) {
                    mma_f16(acc[mt][nt],
                            ta[mt][0], ta[mt][1], ta[mt][2], ta[mt][3],
                            tb[nt][0], tb[nt][1]);
                }
            }
        }
        if (++buf == 3) buf = 0;
    }

    // epilogue
#pragma unroll
    for (int mt = 0; mt < 4; mt++) {
#pragma unroll
        for (int nt = 0; nt < 4; nt++) {
            const int row0 = bm + wm + mt * 16 + g;
            const int col  = bn + wn + nt * 8 + 2 * tg;
            *(float2*)&C[(size_t)row0 * N + col] =
                make_float2(acc[mt][nt][0], acc[mt][nt][1]);
            *(float2*)&C[(size_t)(row0 + 8) * N + col] =
                make_float2(acc[mt][nt][2], acc[mt][nt][3]);
        }
    }
}

// ---------------------------------------------------------------------------
// KV-cache conversion body (t < P): K -> fp16 plane, V -> fp16 transposed.
// ---------------------------------------------------------------------------
__device__ __forceinline__ void prep_cache_body(
    const float* __restrict__ cache_k, const float* __restrict__ cache_v,
    int t0, int kv, int b, char* smraw)
{
    float (*Vs)[68] = (float(*)[68])smraw;
    const int tid = threadIdx.x;
    const int row = tid >> 2, q = tid & 3;
    const int t = t0 + row;

    {
        const float* src = cache_k + ((size_t)(b * KV_ + kv) * CTX_ + t) * HD_ + q * 16;
        uint32_t* dst = g_K16 + ((size_t)(b * KV_ + kv) * CTX_ + t) * 32 + q * 8;
#pragma unroll
        for (int i = 0; i < 4; i++) {
            float4 f = ((const float4*)src)[i];
            dst[2 * i + 0] = h2pack(f.x, f.y);
            dst[2 * i + 1] = h2pack(f.z, f.w);
        }
    }

    const float* vsrc = cache_v + ((size_t)(b * KV_ + kv) * CTX_ + t) * HD_;
#pragma unroll
    for (int i = 0; i < 4; i++)
        *(float4*)&Vs[row][q * 16 + 4 * i] = ((const float4*)(vsrc + q * 16))[i];
    __syncthreads();

    const int hd = tid >> 2, c = tid & 3;
    uint32_t* vdst = g_Vt16 + ((size_t)(b * KV_ + kv) * HD_ + hd) * (CTX_ / 2)
                   + t0 / 2 + c * 8;
#pragma unroll
    for (int i = 0; i < 8; i++) {
        const int tp = c * 8 + i;
        vdst[i] = h2pack(Vs[2 * tp][hd], Vs[2 * tp + 1][hd]);
    }
}

// ---------------------------------------------------------------------------
// Fused Q+K+V projection + KV-cache prep tail. 640 blocks.
// ---------------------------------------------------------------------------
__global__ __launch_bounds__(256, 2) void gemm_qkv_prep(
    const float* __restrict__ cache_k, const float* __restrict__ cache_v)
{
    extern __shared__ char smraw[];
    const int bid = blockIdx.x;
    if (bid < 384) {
        const int bx = bid % 24, bm = (bid / 24) * 128;
        if (bx < 16)
            gemm2_core(g_X16, g_Wq16, g_Q, E_, E_, bm, bx * 128, smraw);
        else if (bx < 20)
            gemm2_core(g_X16, g_Wk16, g_K, KV_ * HD_, E_, bm, (bx - 16) * 128, smraw);
        else
            gemm2_core(g_X16, g_Wv16, g_V, KV_ * HD_, E_, bm, (bx - 20) * 128, smraw);
    } else {
        const int pb = bid - 384;          // 0..255 (t < P only)
        const int t0 = (pb % 16) * 64;
        const int kv = (pb / 16) % 8;
        const int b  = pb / 128;
        prep_cache_body(cache_k, cache_v, t0, kv, b, smraw);
    }
}

__global__ __launch_bounds__(256, 2) void gemm_o(float* __restrict__ out)
{
    extern __shared__ char smraw[];
    gemm2_core(g_A16, g_Wo16, out, E_, E_, blockIdx.y * 128, blockIdx.x * 128, smraw);
}

// ---------------------------------------------------------------------------
// RoPE + fp16 convert: Q -> single plane, new K -> single plane.
// ---------------------------------------------------------------------------
__global__ void rope_split_kernel(const float* __restrict__ cosp,
                                  const float* __restrict__ sinp)
{
    int idx = blockIdx.x * blockDim.x + threadIdx.x;
    constexpr int NH = H_ + KV_;                 // 40
    if (idx >= M_ * NH * 16) return;
    const int p    = idx & 15;
    const int item = idx >> 4;
    const int hh   = item % NH;
    const int row  = item / NH;                  // b*S + s

    const float* cb = cosp + (size_t)row * HD_;
    const float* sb = sinp + (size_t)row * HD_;
    const float c1a = cb[2*p],      c1b = cb[2*p+1];
    const float s1a = sb[2*p],      s1b = sb[2*p+1];
    const float c2a = cb[2*p+32],   c2b = cb[2*p+33];
    const float s2a = sb[2*p+32],   s2b = sb[2*p+33];

    const float* base;
    uint32_t* dst;
    if (hh < H_) {
        base = g_Q + (size_t)row * E_ + hh * HD_;
        dst  = g_Q16 + ((size_t)row * H_ + hh) * 32;
    } else {
        const int kvh = hh - H_;
        base = g_K + (size_t)row * (KV_ * HD_) + kvh * HD_;
        const int b = row / S_, s = row % S_;
        dst  = g_K16 + ((size_t)(b * KV_ + kvh) * CTX_ + P_ + s) * 32;
    }
    const float t1a = base[2*p],    t1b = base[2*p+1];
    const float t2a = base[2*p+32], t2b = base[2*p+33];
    dst[p]      = h2pack(t1a * c1a - t2a * s1a, t1b * c1b - t2b * s1b);
    dst[p + 16] = h2pack(t2a * c2a + t1a * s2a, t2b * c2b + t1b * s2b);
}

// ---------------------------------------------------------------------------
// prep_new_v: new V rows (t >= P) from g_V -> fp16 transposed plane.
// ---------------------------------------------------------------------------
__global__ __launch_bounds__(256) void prep_new_v()
{
    __shared__ float Vs[64][68];
    const int t0 = P_ + blockIdx.x * 64;
    const int kv = blockIdx.y, b = blockIdx.z;
    const int tid = threadIdx.x;
    const int row = tid >> 2, q = tid & 3;
    const int t = t0 + row;

    const float* vsrc = g_V + (size_t)(b * S_ + (t - P_)) * (KV_ * HD_) + kv * HD_;
#pragma unroll
    for (int i = 0; i < 4; i++)
        *(float4*)&Vs[row][q * 16 + 4 * i] = ((const float4*)(vsrc + q * 16))[i];
    __syncthreads();

    const int hd = tid >> 2, c = tid & 3;
    uint32_t* vdst = g_Vt16 + ((size_t)(b * KV_ + kv) * HD_ + hd) * (CTX_ / 2)
                   + t0 / 2 + c * 8;
#pragma unroll
    for (int i = 0; i < 8; i++) {
        const int tp = c * 8 + i;
        vdst[i] = h2pack(Vs[2 * tp][hd], Vs[2 * tp + 1][hd]);
    }
}

// ---------------------------------------------------------------------------
// Flash attention (pure fp16 QK and PV, fp32 accum), BLOCK_M=64, 4 warps,
// 4 blocks/SM, ldmatrix fragment loads.
// ---------------------------------------------------------------------------
constexpr int KT = 64 * 36;   // uint32 per K or V tile (stride 36, 32 used)

__global__ __launch_bounds__(128, 4) void attn_mma()
{
    __shared__ uint32_t KsS[2][KT];
    __shared__ uint32_t VtS[2][KT];

    // longest blocks (largest m0) first
    const int mblk = (int)gridDim.x - 1 - (int)blockIdx.x;
    const int m0 = mblk * 64;
    const int h  = blockIdx.y;
    const int b  = blockIdx.z;
    const int kv = h / G_;
    const int tid  = threadIdx.x;
    const int warp = tid >> 5;
    const int lane = tid & 31;
    const int g    = lane >> 2;
    const int tg   = lane & 3;

    // ldmatrix B-lane addressing (quads: r0-7,k | r0-7,k+4 | r8-15,k | r8-15,k+4)
    const int lB_row = (lane & 7) + ((lane >> 4) & 1) * 8;
    const int lB_col = ((lane >> 3) & 1) * 4;

    const uint32_t* kplane = g_K16 + (size_t)(b * KV_ + kv) * CTX_ * 32;
    const uint32_t* vplane = g_Vt16 + (size_t)(b * KV_ + kv) * HD_ * (CTX_ / 2);
    const int ntile = (P_ + m0 + 64) / 64;

    // tile 0 loads: 512 16B-segments per tile over 128 threads (4 each)
    {
#pragma unroll
        for (int i = 0; i < 4; i++) {
            const int sg = tid + i * 128;
            const int row = sg >> 3, off = (sg & 7) * 4;
            cp16(&KsS[0][row * 36 + off], kplane + (size_t)row * 32 + off);
            cp16(&VtS[0][row * 36 + off], vplane + (size_t)row * (CTX_ / 2) + off);
        }
        asm volatile("cp.async.commit_group;");
    }

    // Q fragments (single fp16 plane), persist across tiles
    uint32_t qf[4][4];
    {
        const uint32_t* q0 = g_Q16 + ((size_t)(b * S_ + m0 + warp * 16 + g)     * H_ + h) * 32;
        const uint32_t* q8 = g_Q16 + ((size_t)(b * S_ + m0 + warp * 16 + g + 8) * H_ + h) * 32;
#pragma unroll
        for (int ks = 0; ks < 4; ks++) {
            qf[ks][0] = q0[tg + 8 * ks];
            qf[ks][1] = q8[tg + 8 * ks];
            qf[ks][2] = q0[tg + 4 + 8 * ks];
            qf[ks][3] = q8[tg + 4 + 8 * ks];
        }
    }

    float o[8][4];
#pragma unroll
    for (int nt = 0; nt < 8; nt++)
#pragma unroll
        for (int r = 0; r < 4; r++) o[nt][r] = 0.f;
    float m0s = -1e30f, m1s = -1e30f, l0 = 0.f, l1 = 0.f;

    const int qpos0 = P_ + m0 + warp * 16 + g;
    const int wmax  = P_ + m0 + warp * 16 + 15;

    for (int it = 0; it < ntile; ++it) {
        const int t0 = it * 64;
        const int buf = it & 1;

        if (it + 1 < ntile) {
            const int nb = (it + 1) & 1;
#pragma unroll
            for (int i = 0; i < 4; i++) {
                const int sg = tid + i * 128;
                const int row = sg >> 3, off = (sg & 7) * 4;
                cp16(&KsS[nb][row * 36 + off],
                     kplane + (size_t)(t0 + 64 + row) * 32 + off);
                cp16(&VtS[nb][row * 36 + off],
                     vplane + (size_t)row * (CTX_ / 2) + (t0 + 64) / 2 + off);
            }
            asm volatile("cp.async.commit_group;");
            asm volatile("cp.async.wait_group 1;");
        } else {
            asm volatile("cp.async.wait_group 0;");
        }
        __syncthreads();

        if (t0 <= wmax) {
            const uint32_t kBase = sm_addr(&KsS[buf][lB_row * 36 + lB_col]);
            const uint32_t vBase = sm_addr(&VtS[buf][lB_row * 36 + lB_col]);

            // --- scores S = Q K^T (ldmatrix x4 covers nt pairs) ---
            float s[8][4];
#pragma unroll
            for (int nt = 0; nt < 8; nt++)
#pragma unroll
                for (int r = 0; r < 4; r++) s[nt][r] = 0.f;

#pragma unroll
            for (int ks = 0; ks < 4; ks++) {
#pragma unroll
                for (int np = 0; np < 4; np++) {
                    uint32_t b0, b1, b2, b3;
                    ldsm4(b0, b1, b2, b3,
                          kBase + (np * 16 * 36 + ks * 8) * 4);
                    mma_f16(s[2*np],   qf[ks][0], qf[ks][1], qf[ks][2], qf[ks][3], b0, b1);
                    mma_f16(s[2*np+1], qf[ks][0], qf[ks][1], qf[ks][2], qf[ks][3], b2, b3);
                }
            }

            // --- scale + causal mask ---
            const bool need_mask = (t0 + 63 > P_ + m0 + warp * 16);
            if (need_mask) {
#pragma unroll
                for (int nt = 0; nt < 8; nt++) {
                    const int col = t0 + 8 * nt + 2 * tg;
#pragma unroll
                    for (int r = 0; r < 4; r++) {
                        const int c  = col + (r & 1);
                        const int qp = (r < 2) ? qpos0 : qpos0 + 8;
                        s[nt][r] = (c > qp) ? -1e30f : s[nt][r] * 0.125f;
                    }
                }
            } else {
#pragma unroll
                for (int nt = 0; nt < 8; nt++)
#pragma unroll
                    for (int r = 0; r < 4; r++) s[nt][r] *= 0.125f;
            }

            // --- online softmax ---
            float mx0 = -1e30f, mx1 = -1e30f;
#pragma unroll
            for (int nt = 0; nt < 8; nt++) {
                mx0 = fmaxf(mx0, fmaxf(s[nt][0], s[nt][1]));
                mx1 = fmaxf(mx1, fmaxf(s[nt][2], s[nt][3]));
            }
            mx0 = fmaxf(mx0, __shfl_xor_sync(0xffffffffu, mx0, 1));
            mx0 = fmaxf(mx0, __shfl_xor_sync(0xffffffffu, mx0, 2));
            mx1 = fmaxf(mx1, __shfl_xor_sync(0xffffffffu, mx1, 1));
            mx1 = fmaxf(mx1, __shfl_xor_sync(0xffffffffu, mx1, 2));

            const float mn0 = fmaxf(m0s, mx0);
            const float mn1 = fmaxf(m1s, mx1);
            const float alpha0 = __expf(m0s - mn0);
            const float alpha1 = __expf(m1s - mn1);
            m0s = mn0; m1s = mn1;

            float sum0 = 0.f, sum1 = 0.f;
#pragma unroll
            for (int nt = 0; nt < 8; nt++) {
                s[nt][0] = __expf(s[nt][0] - mn0);
                s[nt][1] = __expf(s[nt][1] - mn0);
                s[nt][2] = __expf(s[nt][2] - mn1);
                s[nt][3] = __expf(s[nt][3] - mn1);
                sum0 += s[nt][0] + s[nt][1];
                sum1 += s[nt][2] + s[nt][3];
            }
            sum0 += __shfl_xor_sync(0xffffffffu, sum0, 1);
            sum0 += __shfl_xor_sync(0xffffffffu, sum0, 2);
            sum1 += __shfl_xor_sync(0xffffffffu, sum1, 1);
            sum1 += __shfl_xor_sync(0xffffffffu, sum1, 2);
            l0 = l0 * alpha0 + sum0;
            l1 = l1 * alpha1 + sum1;

#pragma unroll
            for (int nt = 0; nt < 8; nt++) {
                o[nt][0] *= alpha0; o[nt][1] *= alpha0;
                o[nt][2] *= alpha1; o[nt][3] *= alpha1;
            }

            // --- O += P V (ldmatrix x4 covers nt pairs) ---
#pragma unroll
            for (int ks = 0; ks < 4; ks++) {
                uint32_t a0 = h2pack(s[2 * ks][0],     s[2 * ks][1]);
                uint32_t a1 = h2pack(s[2 * ks][2],     s[2 * ks][3]);
                uint32_t a2 = h2pack(s[2 * ks + 1][0], s[2 * ks + 1][1]);
                uint32_t a3 = h2pack(s[2 * ks + 1][2], s[2 * ks + 1][3]);
#pragma unroll
                for (int np = 0; np < 4; np++) {
                    uint32_t b0, b1, b2, b3;
                    ldsm4(b0, b1, b2, b3,
                          vBase + (np * 16 * 36 + ks * 8) * 4);
                    mma_f16(o[2*np],   a0, a1, a2, a3, b0, b1);
                    mma_f16(o[2*np+1], a0, a1, a2, a3, b2, b3);
                }
            }
        }

        __syncthreads();
    }

    // --- epilogue: write fp16 plane for the O projection ---
    const float inv0 = 1.f / l0;
    const float inv1 = 1.f / l1;
    const size_t row0  = (size_t)(b * S_ + m0 + warp * 16 + g);
    const size_t base0 = row0 * (E_ / 2) + h * (HD_ / 2) + tg;
    const size_t base8 = base0 + 4 * E_;     // +8 rows (8 * E/2)
#pragma unroll
    for (int nt = 0; nt < 8; nt++) {
        g_A16[base0 + 4 * nt] = h2pack(o[nt][0] * inv0, o[nt][1] * inv0);
        g_A16[base8 + 4 * nt] = h2pack(o[nt][2] * inv1, o[nt][3] * inv1);
    }
}

// ---------------------------------------------------------------------------
// Launcher
// ---------------------------------------------------------------------------
extern "C" void kernel_launch(void* const* d_in, const int* in_sizes, int n_in,
                              void* d_out, int out_size)
{
    const float* x       = (const float*)d_in[0];
    const float* cosp    = (const float*)d_in[1];
    const float* sinp    = (const float*)d_in[2];
    // d_in[3] = mask (causal; computed analytically)
    const float* cache_k = (const float*)d_in[4];
    const float* cache_v = (const float*)d_in[5];
    const float* Wq      = (const float*)d_in[6];
    const float* Wk      = (const float*)d_in[7];
    const float* Wv      = (const float*)d_in[8];
    const float* Wo      = (const float*)d_in[9];
    float* out           = (float*)d_out;

    cudaFuncSetAttribute(gemm_qkv_prep, cudaFuncAttributeMaxDynamicSharedMemorySize, GSM2);
    cudaFuncSetAttribute(gemm_o,        cudaFuncAttributeMaxDynamicSharedMemorySize, GSM2);

    // 0) fp16 planes: x + weights (one launch)
    prep_all<<<dim3(M_ * E_ / 2 / 256, 5), 256>>>(x, Wq, Wk, Wv, Wo);

    // 1) fused Q/K/V projections + KV-cache conversion in the wave tail
    gemm_qkv_prep<<<640, 256, GSM2>>>(cache_k, cache_v);

    // 2) RoPE + fp16 convert of Q and new K
    {
        const int total = M_ * (H_ + KV_) * 16;
        rope_split_kernel<<<(total + 255) / 256, 256>>>(cosp, sinp);
    }

    // 3) new V rows -> transposed fp16 plane
    prep_new_v<<<dim3(S_ / 64, KV_, B_), 256>>>();

    // 4) flash attention (pure fp16 mma, ldmatrix, BLOCK_M=64, 4 blocks/SM)
    attn_mma<<<dim3(S_ / 64, H_, B_), 128>>>();

    // 5) output projection (plain fp16, 3-stage pipeline, ldmatrix)
    gemm_o<<<dim3(16, 16), 256, GSM2>>>(out);
}

// round 14
// speedup vs baseline: 1.7572x; 1.0091x over previous
#include <cuda_runtime.h>
#include <cuda_fp16.h>
#include <math.h>
#include <stdint.h>

// ---------------------------------------------------------------------------
// Problem constants (LlamaAttention: B=2,S=1024,P=1024,E=2048,H=32,KV=8,HD=64)
// ---------------------------------------------------------------------------
constexpr int B_   = 2;
constexpr int S_   = 1024;
constexpr int P_   = 1024;
constexpr int E_   = 2048;
constexpr int H_   = 32;
constexpr int KV_  = 8;
constexpr int HD_  = 64;
constexpr int G_   = H_ / KV_;        // 4
constexpr int CTX_ = P_ + S_;         // 2048
constexpr int M_   = B_ * S_;         // 2048 rows of tokens

// ---------------------------------------------------------------------------
// Scratch (static device allocations are the sanctioned workaround)
// ---------------------------------------------------------------------------
__device__ float    g_Q[(size_t)M_ * E_];                   // fp32 Q (pre-rope)
__device__ float    g_K[(size_t)M_ * KV_ * HD_];            // fp32 new K (pre-rope)
__device__ float    g_V[(size_t)M_ * KV_ * HD_];            // fp32 new V
__device__ uint32_t g_X16[(size_t)M_ * E_ / 2];             // x fp16 plane
__device__ uint32_t g_A16[(size_t)M_ * E_ / 2];             // attn out fp16 plane
__device__ uint32_t g_Wq16[(size_t)E_ * E_ / 2];            // fp16 packed weights
__device__ uint32_t g_Wk16[(size_t)KV_ * HD_ * E_ / 2];
__device__ uint32_t g_Wv16[(size_t)KV_ * HD_ * E_ / 2];
__device__ uint32_t g_Wo16[(size_t)E_ * E_ / 2];
__device__ uint32_t g_Q16[(size_t)M_ * H_ * 32];            // Q fp16 (pre-scaled by 1/8)
__device__ uint32_t g_K16[(size_t)B_ * KV_ * CTX_ * 32];    // K fp16 [b][kv][t][hd/2]
__device__ uint32_t g_Vt16[(size_t)B_ * KV_ * HD_ * (CTX_/2)]; // V^T fp16 [b][kv][hd][t/2]

// ---------------------------------------------------------------------------
// fp16 helpers
// ---------------------------------------------------------------------------
__device__ __forceinline__ uint32_t h2pack(float a, float b)
{
    __half2 h = __floats2half2_rn(a, b);
    return *reinterpret_cast<uint32_t*>(&h);
}

__device__ __forceinline__ void mma_f16(float c[4],
    uint32_t a0, uint32_t a1, uint32_t a2, uint32_t a3,
    uint32_t b0, uint32_t b1)
{
    asm volatile(
        "mma.sync.aligned.m16n8k16.row.col.f32.f16.f16.f32 "
        "{%0,%1,%2,%3}, {%4,%5,%6,%7}, {%8,%9}, {%0,%1,%2,%3};"
        : "+f"(c[0]), "+f"(c[1]), "+f"(c[2]), "+f"(c[3])
        : "r"(a0), "r"(a1), "r"(a2), "r"(a3), "r"(b0), "r"(b1));
}

__device__ __forceinline__ void cp16(void* smem_dst, const void* gsrc)
{
    uint32_t d = (uint32_t)__cvta_generic_to_shared(smem_dst);
    asm volatile("cp.async.cg.shared.global [%0], [%1], 16;" :: "r"(d), "l"(gsrc));
}

__device__ __forceinline__ uint32_t sm_addr(const void* p)
{
    return (uint32_t)__cvta_generic_to_shared(p);
}

__device__ __forceinline__ void ldsm4(uint32_t& r0, uint32_t& r1,
                                      uint32_t& r2, uint32_t& r3, uint32_t addr)
{
    asm volatile("ldmatrix.sync.aligned.m8n8.x4.shared.b16 {%0,%1,%2,%3}, [%4];"
                 : "=r"(r0), "=r"(r1), "=r"(r2), "=r"(r3) : "r"(addr));
}

// ---------------------------------------------------------------------------
// prep_all: single launch converting x and all weights to fp16 planes.
// ---------------------------------------------------------------------------
__global__ void prep_all(const float* __restrict__ x,
                         const float* __restrict__ Wq, const float* __restrict__ Wk,
                         const float* __restrict__ Wv, const float* __restrict__ Wo)
{
    const int i = blockIdx.x * blockDim.x + threadIdx.x;
    const int y = blockIdx.y;
    if (y == 0) {
        float2 f = *(const float2*)(x + 2 * i);
        g_X16[i] = h2pack(f.x, f.y);
    } else if (y == 1) {
        float2 f = *(const float2*)(Wq + 2 * i);
        g_Wq16[i] = h2pack(f.x, f.y);
    } else if (y == 2) {
        if (i < KV_ * HD_ * E_ / 2) {
            float2 f = *(const float2*)(Wk + 2 * i);
            g_Wk16[i] = h2pack(f.x, f.y);
        }
    } else if (y == 3) {
        if (i < KV_ * HD_ * E_ / 2) {
            float2 f = *(const float2*)(Wv + 2 * i);
            g_Wv16[i] = h2pack(f.x, f.y);
        }
    } else {
        float2 f = *(const float2*)(Wo + 2 * i);
        g_Wo16[i] = h2pack(f.x, f.y);
    }
}

// ---------------------------------------------------------------------------
// Plain fp16 GEMM core (unchanged from R12).
// ---------------------------------------------------------------------------
constexpr int GSTR2 = 20;
constexpr int PST   = 128 * GSTR2;
constexpr int GSM2  = 3 * 2 * PST * 4;   // 61440 B

__device__ __forceinline__ void gemm2_stage(
    const uint32_t* __restrict__ A, const uint32_t* __restrict__ Bh,
    int Kp, int bm, int bn, int kp0, uint32_t* Ad, uint32_t* Bd, int tid)
{
#pragma unroll
    for (int i = 0; i < 2; i++) {
        int c = tid * 2 + i;
        int row = c >> 2, off = (c & 3) * 4;
        cp16(Ad + row * GSTR2 + off, A  + (size_t)(bm + row) * Kp + kp0 + off);
        cp16(Bd + row * GSTR2 + off, Bh + (size_t)(bn + row) * Kp + kp0 + off);
    }
    asm volatile("cp.async.commit_group;" ::: "memory");
}

__device__ __forceinline__ void gemm2_core(
    const uint32_t* __restrict__ A, const uint32_t* __restrict__ Bh,
    float* __restrict__ C, int N, int K, int bm, int bn, char* smraw)
{
    uint32_t* As = (uint32_t*)smraw;
    uint32_t* Bs = (uint32_t*)(smraw + 3 * PST * 4);
    const int tid  = threadIdx.x;
    const int warp = tid >> 5;
    const int lane = tid & 31;
    const int g    = lane >> 2;
    const int tg   = lane & 3;
    const int wm   = (warp >> 2) * 64;
    const int wn   = (warp & 3) * 32;
    const int Kp   = K / 2;

    const int lA_row = (lane & 7) + ((lane >> 3) & 1) * 8;
    const int lA_col = ((lane >> 4) & 1) * 4;
    const int lB_row = (lane & 7) + ((lane >> 4) & 1) * 8;
    const int lB_col = ((lane >> 3) & 1) * 4;

    float acc[4][4][4];
#pragma unroll
    for (int i = 0; i < 4; i++)
#pragma unroll
        for (int j = 0; j < 4; j++)
#pragma unroll
            for (int r = 0; r < 4; r++) acc[i][j][r] = 0.f;

    const int nst = K / 32;
    gemm2_stage(A, Bh, Kp, bm, bn, 0,  As,       Bs,       tid);
    gemm2_stage(A, Bh, Kp, bm, bn, 16, As + PST, Bs + PST, tid);

    int buf = 0;
    for (int s = 0; s < nst; s++) {
        if (s + 1 < nst)
            asm volatile("cp.async.wait_group 1;" ::: "memory");
        else
            asm volatile("cp.async.wait_group 0;" ::: "memory");
        __syncthreads();

        if (s + 2 < nst) {
            int nb = buf + 2; if (nb >= 3) nb -= 3;
            gemm2_stage(A, Bh, Kp, bm, bn, (s + 2) * 16,
                        As + nb * PST, Bs + nb * PST, tid);
        }

        const uint32_t* Ab = As + buf * PST;
        const uint32_t* Bb = Bs + buf * PST;
        const uint32_t aBase = sm_addr(Ab + (wm + lA_row) * GSTR2 + lA_col);
        const uint32_t bBase = sm_addr(Bb + (wn + lB_row) * GSTR2 + lB_col);

#pragma unroll
        for (int ks = 0; ks < 2; ks++) {
            const uint32_t ko = ks * 32;
            uint32_t ta[4][4];
#pragma unroll
            for (int mt = 0; mt < 4; mt++)
                ldsm4(ta[mt][0], ta[mt][1], ta[mt][2], ta[mt][3],
                      aBase + mt * 16 * GSTR2 * 4 + ko);
            uint32_t tb[4][2];
#pragma unroll
            for (int np = 0; np < 2; np++)
                ldsm4(tb[2*np][0], tb[2*np][1], tb[2*np+1][0], tb[2*np+1][1],
                      bBase + np * 16 * GSTR2 * 4 + ko);
#pragma unroll
            for (int mt = 0; mt < 4; mt++) {
#pragma unroll
                for (int nt = 0; nt < 4; nt++) {
                    mma_f16(acc[mt][nt],
                            ta[mt][0], ta[mt][1], ta[mt][2], ta[mt][3],
                            tb[nt][0], tb[nt][1]);
                }
            }
        }
        if (++buf == 3) buf = 0;
    }

#pragma unroll
    for (int mt = 0; mt < 4; mt++) {
#pragma unroll
        for (int nt = 0; nt < 4; nt++) {
            const int row0 = bm + wm + mt * 16 + g;
            const int col  = bn + wn + nt * 8 + 2 * tg;
            *(float2*)&C[(size_t)row0 * N + col] =
                make_float2(acc[mt][nt][0], acc[mt][nt][1]);
            *(float2*)&C[(size_t)(row0 + 8) * N + col] =
                make_float2(acc[mt][nt][2], acc[mt][nt][3]);
        }
    }
}

// ---------------------------------------------------------------------------
// KV-cache conversion body (t < P).
// ---------------------------------------------------------------------------
__device__ __forceinline__ void prep_cache_body(
    const float* __restrict__ cache_k, const float* __restrict__ cache_v,
    int t0, int kv, int b, char* smraw)
{
    float (*Vs)[68] = (float(*)[68])smraw;
    const int tid = threadIdx.x;
    const int row = tid >> 2, q = tid & 3;
    const int t = t0 + row;

    {
        const float* src = cache_k + ((size_t)(b * KV_ + kv) * CTX_ + t) * HD_ + q * 16;
        uint32_t* dst = g_K16 + ((size_t)(b * KV_ + kv) * CTX_ + t) * 32 + q * 8;
#pragma unroll
        for (int i = 0; i < 4; i++) {
            float4 f = ((const float4*)src)[i];
            dst[2 * i + 0] = h2pack(f.x, f.y);
            dst[2 * i + 1] = h2pack(f.z, f.w);
        }
    }

    const float* vsrc = cache_v + ((size_t)(b * KV_ + kv) * CTX_ + t) * HD_;
#pragma unroll
    for (int i = 0; i < 4; i++)
        *(float4*)&Vs[row][q * 16 + 4 * i] = ((const float4*)(vsrc + q * 16))[i];
    __syncthreads();

    const int hd = tid >> 2, c = tid & 3;
    uint32_t* vdst = g_Vt16 + ((size_t)(b * KV_ + kv) * HD_ + hd) * (CTX_ / 2)
                   + t0 / 2 + c * 8;
#pragma unroll
    for (int i = 0; i < 8; i++) {
        const int tp = c * 8 + i;
        vdst[i] = h2pack(Vs[2 * tp][hd], Vs[2 * tp + 1][hd]);
    }
}

// ---------------------------------------------------------------------------
// Fused Q+K+V projection + KV-cache prep tail. 640 blocks.
// ---------------------------------------------------------------------------
__global__ __launch_bounds__(256, 2) void gemm_qkv_prep(
    const float* __restrict__ cache_k, const float* __restrict__ cache_v)
{
    extern __shared__ char smraw[];
    const int bid = blockIdx.x;
    if (bid < 384) {
        const int bx = bid % 24, bm = (bid / 24) * 128;
        if (bx < 16)
            gemm2_core(g_X16, g_Wq16, g_Q, E_, E_, bm, bx * 128, smraw);
        else if (bx < 20)
            gemm2_core(g_X16, g_Wk16, g_K, KV_ * HD_, E_, bm, (bx - 16) * 128, smraw);
        else
            gemm2_core(g_X16, g_Wv16, g_V, KV_ * HD_, E_, bm, (bx - 20) * 128, smraw);
    } else {
        const int pb = bid - 384;
        const int t0 = (pb % 16) * 64;
        const int kv = (pb / 16) % 8;
        const int b  = pb / 128;
        prep_cache_body(cache_k, cache_v, t0, kv, b, smraw);
    }
}

__global__ __launch_bounds__(256, 2) void gemm_o(float* __restrict__ out)
{
    extern __shared__ char smraw[];
    gemm2_core(g_A16, g_Wo16, out, E_, E_, blockIdx.y * 128, blockIdx.x * 128, smraw);
}

// ---------------------------------------------------------------------------
// rope_prep: RoPE+convert (Q pre-scaled by 1/8, new K) + new-V transpose.
// 1-D grid of 5376 blocks: bid<5120 rope, else new-V.
// ---------------------------------------------------------------------------
__global__ __launch_bounds__(256) void rope_prep(
    const float* __restrict__ cosp, const float* __restrict__ sinp)
{
    __shared__ float Vs[64][68];
    const int bid = blockIdx.x;
    if (bid < 5120) {
        const int idx = bid * 256 + threadIdx.x;
        constexpr int NH = H_ + KV_;                 // 40
        const int p    = idx & 15;
        const int item = idx >> 4;
        const int hh   = item % NH;
        const int row  = item / NH;                  // b*S + s

        const float* cb = cosp + (size_t)row * HD_;
        const float* sb = sinp + (size_t)row * HD_;
        float c1a = cb[2*p],      c1b = cb[2*p+1];
        float s1a = sb[2*p],      s1b = sb[2*p+1];
        float c2a = cb[2*p+32],   c2b = cb[2*p+33];
        float s2a = sb[2*p+32],   s2b = sb[2*p+33];

        const float* base;
        uint32_t* dst;
        if (hh < H_) {
            base = g_Q + (size_t)row * E_ + hh * HD_;
            dst  = g_Q16 + ((size_t)row * H_ + hh) * 32;
            // fold softmax scale 1/sqrt(64) into Q
            c1a *= 0.125f; c1b *= 0.125f; s1a *= 0.125f; s1b *= 0.125f;
            c2a *= 0.125f; c2b *= 0.125f; s2a *= 0.125f; s2b *= 0.125f;
        } else {
            const int kvh = hh - H_;
            base = g_K + (size_t)row * (KV_ * HD_) + kvh * HD_;
            const int b = row / S_, s = row % S_;
            dst  = g_K16 + ((size_t)(b * KV_ + kvh) * CTX_ + P_ + s) * 32;
        }
        const float t1a = base[2*p],    t1b = base[2*p+1];
        const float t2a = base[2*p+32], t2b = base[2*p+33];
        dst[p]      = h2pack(t1a * c1a - t2a * s1a, t1b * c1b - t2b * s1b);
        dst[p + 16] = h2pack(t2a * c2a + t1a * s2a, t2b * c2b + t1b * s2b);
    } else {
        const int pb = bid - 5120;                 // 0..255
        const int t0 = P_ + (pb % 16) * 64;
        const int kv = (pb / 16) % 8;
        const int b  = pb / 128;
        const int tid = threadIdx.x;
        const int row = tid >> 2, q = tid & 3;
        const int t = t0 + row;

        const float* vsrc = g_V + (size_t)(b * S_ + (t - P_)) * (KV_ * HD_) + kv * HD_;
#pragma unroll
        for (int i = 0; i < 4; i++)
            *(float4*)&Vs[row][q * 16 + 4 * i] = ((const float4*)(vsrc + q * 16))[i];
        __syncthreads();

        const int hd = tid >> 2, c = tid & 3;
        uint32_t* vdst = g_Vt16 + ((size_t)(b * KV_ + kv) * HD_ + hd) * (CTX_ / 2)
                       + t0 / 2 + c * 8;
#pragma unroll
        for (int i = 0; i < 8; i++) {
            const int tp = c * 8 + i;
            vdst[i] = h2pack(Vs[2 * tp][hd], Vs[2 * tp + 1][hd]);
        }
    }
}

// ---------------------------------------------------------------------------
// Flash attention: BLOCK_M=64, BLOCK_N=128 supertiles, one softmax per 128
// keys. 128 threads (4 warps), ldmatrix frags, double-buffered cp.async.
// ---------------------------------------------------------------------------
constexpr int KTS  = 128 * 36;              // uint32 per K supertile
constexpr int VTS  = 64 * 68;               // uint32 per V supertile
constexpr int ATTN_SMEM = (2 * KTS + 2 * VTS) * 4;   // 71680 B

__global__ __launch_bounds__(128, 3) void attn_mma()
{
    extern __shared__ uint32_t dsm[];
    uint32_t* KsS[2] = { dsm,           dsm + KTS };
    uint32_t* VtS[2] = { dsm + 2 * KTS, dsm + 2 * KTS + VTS };

    // longest blocks (largest m0) first
    const int mblk = (int)gridDim.x - 1 - (int)blockIdx.x;
    const int m0 = mblk * 64;
    const int h  = blockIdx.y;
    const int b  = blockIdx.z;
    const int kv = h / G_;
    const int tid  = threadIdx.x;
    const int warp = tid >> 5;
    const int lane = tid & 31;
    const int g    = lane >> 2;
    const int tg   = lane & 3;

    const int lB_row = (lane & 7) + ((lane >> 4) & 1) * 8;
    const int lB_col = ((lane >> 3) & 1) * 4;

    const uint32_t* kplane = g_K16 + (size_t)(b * KV_ + kv) * CTX_ * 32;
    const uint32_t* vplane = g_Vt16 + (size_t)(b * KV_ + kv) * HD_ * (CTX_ / 2);
    const int ntile = (P_ + m0 + 64 + 127) >> 7;   // 128-key supertiles

    // supertile 0 loads: K 1024 segs + V 1024 segs over 128 threads
    {
#pragma unroll
        for (int i = 0; i < 8; i++) {
            const int sg = tid + i * 128;          // 0..1023
            const int kr = sg >> 3, ko = (sg & 7) * 4;
            cp16(KsS[0] + kr * 36 + ko, kplane + (size_t)kr * 32 + ko);
            const int vr = sg >> 4, vo = (sg & 15) * 4;
            cp16(VtS[0] + vr * 68 + vo, vplane + (size_t)vr * (CTX_ / 2) + vo);
        }
        asm volatile("cp.async.commit_group;");
    }

    // Q fragments (pre-scaled fp16 plane), persist across tiles
    uint32_t qf[4][4];
    {
        const uint32_t* q0 = g_Q16 + ((size_t)(b * S_ + m0 + warp * 16 + g)     * H_ + h) * 32;
        const uint32_t* q8 = g_Q16 + ((size_t)(b * S_ + m0 + warp * 16 + g + 8) * H_ + h) * 32;
#pragma unroll
        for (int ks = 0; ks < 4; ks++) {
            qf[ks][0] = q0[tg + 8 * ks];
            qf[ks][1] = q8[tg + 8 * ks];
            qf[ks][2] = q0[tg + 4 + 8 * ks];
            qf[ks][3] = q8[tg + 4 + 8 * ks];
        }
    }

    float o[8][4];
#pragma unroll
    for (int nt = 0; nt < 8; nt++)
#pragma unroll
        for (int r = 0; r < 4; r++) o[nt][r] = 0.f;
    float m0s = -1e30f, m1s = -1e30f, l0 = 0.f, l1 = 0.f;

    const int qpos0 = P_ + m0 + warp * 16 + g;
    const int wmax  = P_ + m0 + warp * 16 + 15;

    for (int it = 0; it < ntile; ++it) {
        const int t0 = it * 128;
        const int buf = it & 1;

        if (it + 1 < ntile) {
            const int nb = (it + 1) & 1;
#pragma unroll
            for (int i = 0; i < 8; i++) {
                const int sg = tid + i * 128;
                const int kr = sg >> 3, ko = (sg & 7) * 4;
                cp16(KsS[nb] + kr * 36 + ko,
                     kplane + (size_t)(t0 + 128 + kr) * 32 + ko);
                const int vr = sg >> 4, vo = (sg & 15) * 4;
                cp16(VtS[nb] + vr * 68 + vo,
                     vplane + (size_t)vr * (CTX_ / 2) + (t0 + 128) / 2 + vo);
            }
            asm volatile("cp.async.commit_group;");
            asm volatile("cp.async.wait_group 1;");
        } else {
            asm volatile("cp.async.wait_group 0;");
        }
        __syncthreads();

        if (t0 <= wmax) {
            const uint32_t kBase = sm_addr(KsS[buf] + lB_row * 36 + lB_col);
            const uint32_t vBase = sm_addr(VtS[buf] + lB_row * 68 + lB_col);

            // --- scores S = Q K^T over 128 keys (16 nt) ---
            float s[16][4];
#pragma unroll
            for (int nt = 0; nt < 16; nt++)
#pragma unroll
                for (int r = 0; r < 4; r++) s[nt][r] = 0.f;

#pragma unroll
            for (int ks = 0; ks < 4; ks++) {
#pragma unroll
                for (int np = 0; np < 8; np++) {
                    uint32_t b0, b1, b2, b3;
                    ldsm4(b0, b1, b2, b3,
                          kBase + (np * 16 * 36 + ks * 8) * 4);
                    mma_f16(s[2*np],   qf[ks][0], qf[ks][1], qf[ks][2], qf[ks][3], b0, b1);
                    mma_f16(s[2*np+1], qf[ks][0], qf[ks][1], qf[ks][2], qf[ks][3], b2, b3);
                }
            }

            // --- causal mask (scale already folded into Q) ---
            const bool need_mask = (t0 + 127 > P_ + m0 + warp * 16);
            if (need_mask) {
#pragma unroll
                for (int nt = 0; nt < 16; nt++) {
                    const int col = t0 + 8 * nt + 2 * tg;
#pragma unroll
                    for (int r = 0; r < 4; r++) {
                        const int c  = col + (r & 1);
                        const int qp = (r < 2) ? qpos0 : qpos0 + 8;
                        if (c > qp) s[nt][r] = -1e30f;
                    }
                }
            }

            // --- online softmax (once per 128 keys) ---
            float mx0 = -1e30f, mx1 = -1e30f;
#pragma unroll
            for (int nt = 0; nt < 16; nt++) {
                mx0 = fmaxf(mx0, fmaxf(s[nt][0], s[nt][1]));
                mx1 = fmaxf(mx1, fmaxf(s[nt][2], s[nt][3]));
            }
            mx0 = fmaxf(mx0, __shfl_xor_sync(0xffffffffu, mx0, 1));
            mx0 = fmaxf(mx0, __shfl_xor_sync(0xffffffffu, mx0, 2));
            mx1 = fmaxf(mx1, __shfl_xor_sync(0xffffffffu, mx1, 1));
            mx1 = fmaxf(mx1, __shfl_xor_sync(0xffffffffu, mx1, 2));

            const float mn0 = fmaxf(m0s, mx0);
            const float mn1 = fmaxf(m1s, mx1);
            const float alpha0 = __expf(m0s - mn0);
            const float alpha1 = __expf(m1s - mn1);
            m0s = mn0; m1s = mn1;

            float sum0 = 0.f, sum1 = 0.f;
#pragma unroll
            for (int nt = 0; nt < 16; nt++) {
                s[nt][0] = __expf(s[nt][0] - mn0);
                s[nt][1] = __expf(s[nt][1] - mn0);
                s[nt][2] = __expf(s[nt][2] - mn1);
                s[nt][3] = __expf(s[nt][3] - mn1);
                sum0 += s[nt][0] + s[nt][1];
                sum1 += s[nt][2] + s[nt][3];
            }
            sum0 += __shfl_xor_sync(0xffffffffu, sum0, 1);
            sum0 += __shfl_xor_sync(0xffffffffu, sum0, 2);
            sum1 += __shfl_xor_sync(0xffffffffu, sum1, 1);
            sum1 += __shfl_xor_sync(0xffffffffu, sum1, 2);
            l0 = l0 * alpha0 + sum0;
            l1 = l1 * alpha1 + sum1;

#pragma unroll
            for (int nt = 0; nt < 8; nt++) {
                o[nt][0] *= alpha0; o[nt][1] *= alpha0;
                o[nt][2] *= alpha1; o[nt][3] *= alpha1;
            }

            // --- O += P V over 128 keys (8 k-steps) ---
#pragma unroll
            for (int ks = 0; ks < 8; ks++) {
                uint32_t a0 = h2pack(s[2 * ks][0],     s[2 * ks][1]);
                uint32_t a1 = h2pack(s[2 * ks][2],     s[2 * ks][3]);
                uint32_t a2 = h2pack(s[2 * ks + 1][0], s[2 * ks + 1][1]);
                uint32_t a3 = h2pack(s[2 * ks + 1][2], s[2 * ks + 1][3]);
#pragma unroll
                for (int np = 0; np < 4; np++) {
                    uint32_t b0, b1, b2, b3;
                    ldsm4(b0, b1, b2, b3,
                          vBase + (np * 16 * 68 + ks * 8) * 4);
                    mma_f16(o[2*np],   a0, a1, a2, a3, b0, b1);
                    mma_f16(o[2*np+1], a0, a1, a2, a3, b2, b3);
                }
            }
        }

        __syncthreads();
    }

    // --- epilogue: write fp16 plane for the O projection ---
    const float inv0 = 1.f / l0;
    const float inv1 = 1.f / l1;
    const size_t row0  = (size_t)(b * S_ + m0 + warp * 16 + g);
    const size_t base0 = row0 * (E_ / 2) + h * (HD_ / 2) + tg;
    const size_t base8 = base0 + 4 * E_;     // +8 rows (8 * E/2)
#pragma unroll
    for (int nt = 0; nt < 8; nt++) {
        g_A16[base0 + 4 * nt] = h2pack(o[nt][0] * inv0, o[nt][1] * inv0);
        g_A16[base8 + 4 * nt] = h2pack(o[nt][2] * inv1, o[nt][3] * inv1);
    }
}

// ---------------------------------------------------------------------------
// Launcher
// ---------------------------------------------------------------------------
extern "C" void kernel_launch(void* const* d_in, const int* in_sizes, int n_in,
                              void* d_out, int out_size)
{
    const float* x       = (const float*)d_in[0];
    const float* cosp    = (const float*)d_in[1];
    const float* sinp    = (const float*)d_in[2];
    // d_in[3] = mask (causal; computed analytically)
    const float* cache_k = (const float*)d_in[4];
    const float* cache_v = (const float*)d_in[5];
    const float* Wq      = (const float*)d_in[6];
    const float* Wk      = (const float*)d_in[7];
    const float* Wv      = (const float*)d_in[8];
    const float* Wo      = (const float*)d_in[9];
    float* out           = (float*)d_out;

    cudaFuncSetAttribute(gemm_qkv_prep, cudaFuncAttributeMaxDynamicSharedMemorySize, GSM2);
    cudaFuncSetAttribute(gemm_o,        cudaFuncAttributeMaxDynamicSharedMemorySize, GSM2);
    cudaFuncSetAttribute(attn_mma,      cudaFuncAttributeMaxDynamicSharedMemorySize, ATTN_SMEM);

    // 0) fp16 planes: x + weights (one launch)
    prep_all<<<dim3(M_ * E_ / 2 / 256, 5), 256>>>(x, Wq, Wk, Wv, Wo);

    // 1) fused Q/K/V projections + KV-cache conversion in the wave tail
    gemm_qkv_prep<<<640, 256, GSM2>>>(cache_k, cache_v);

    // 2) RoPE (+1/8 scale on Q) + new-K convert + new-V transpose
    rope_prep<<<5376, 256>>>(cosp, sinp);

    // 3) flash attention (fp16 mma, BLOCK_N=128 supertiles)
    attn_mma<<<dim3(S_ / 64, H_, B_), 128, ATTN_SMEM>>>();

    // 4) output projection
    gemm_o<<<dim3(16, 16), 256, GSM2>>>(out);
}